// round 11
// baseline (speedup 1.0000x reference)
#include <cuda_runtime.h>

#define BSZ  2048
#define SEQL 50
#define NP   (BSZ*SEQL)      /* 102400 pairs */
#define ATTD 64
#define HIDD 128
#define G4   512             /* 4*HID gates */

typedef unsigned long long ull;

/* ---------------- device scratch (no cudaMalloc allowed) ---------------- */
__device__ float  g_ctx[(size_t)NP * ATTD];        /* [s][b][64]  26 MB  */
__device__ float  g_xg [(size_t)NP * G4];          /* [s][b][512] 210 MB */
__device__ float4 g_whh4t[(HIDD/4) * G4];          /* [kq][col] packed W_hh^T */
__device__ float  g_M[4*7*20];                     /* bilinear att matrices */
__device__ float  g_G[20*64];                      /* folded Wv*Ffus (+bv)  */

/* ---------------- f32x2 helpers ----------------------------------------- */
__device__ __forceinline__ void fma2(ull& d, ull a, ull b){
    asm("fma.rn.f32x2 %0, %1, %2, %0;" : "+l"(d) : "l"(a), "l"(b));
}
__device__ __forceinline__ float2 unpk(ull v){
    float2 r; asm("mov.b64 {%0, %1}, %2;" : "=f"(r.x), "=f"(r.y) : "l"(v)); return r;
}
__device__ __forceinline__ float hsum2(ull v){ float2 f = unpk(v); return f.x + f.y; }
__device__ __forceinline__ float sigm(float x){ return 1.f/(1.f + __expf(-x)); }
__device__ __forceinline__ float tanhfast(float x){ return 1.f - 2.f/(__expf(2.f*x) + 1.f); }

/* ============ kernel P: fold weights into M (4x7x20) and G (20x64) ====== */
__global__ void k_prep(
    const float* __restrict__ Wfus, const float* __restrict__ bfus,
    const float* __restrict__ Wk,   const float* __restrict__ bk,
    const float* __restrict__ Wq,   const float* __restrict__ bq,
    const float* __restrict__ Wv,   const float* __restrict__ bv)
{
    __shared__ float sQ[16*20];
    const int bid = blockIdx.x, tid = threadIdx.x;      /* <<<24,128>>> */
    if (bid < 4){
        int h = bid;
        for (int i = tid; i < 320; i += 128){
            int k = i % 20, d = i / 20, od = h*16 + d;
            float acc = (k == 19) ? bq[od] : 0.f;
            for (int c = 0; c < 64; c++){
                float f = (k < 19) ? Wfus[c*19 + k] : bfus[c];
                acc += Wq[od*64 + c] * f;
            }
            sQ[i] = acc;
        }
        __syncthreads();
        for (int i = tid; i < 140; i += 128){
            int k = i % 20, dp = i / 20;
            float acc = 0.f;
            for (int d = 0; d < 16; d++){
                int o = h*16 + d;
                float wk = (dp < 6) ? Wk[o*6 + dp] : bk[o];
                acc += wk * sQ[d*20 + k];
            }
            g_M[h*140 + dp*20 + k] = 0.25f * acc;
        }
    } else {
        int k = bid - 4;                                /* 0..19 */
        for (int o = tid; o < 64; o += 128){
            float acc = (k == 19) ? bv[o] : 0.f;
            for (int c = 0; c < 64; c++){
                float f = (k < 19) ? Wfus[c*19 + k] : bfus[c];
                acc += Wv[o*64 + c] * f;
            }
            g_G[k*64 + o] = acc;
        }
    }
}

/* ============ kernel 0: transpose+pack W_hh -> [kq][col] float4 ========= */
__global__ void k_pack(const float* __restrict__ Whh){
    int t = threadIdx.x, kq = blockIdx.x;             /* <<<32,512>>> */
    g_whh4t[kq*G4 + t] = make_float4(Whh[t*HIDD + 4*kq],   Whh[t*HIDD + 4*kq+1],
                                     Whh[t*HIDD + 4*kq+2], Whh[t*HIDD + 4*kq+3]);
}

/* ============ kernel 1: attention via precomputed bilinear form (R10) === */
__global__ void __launch_bounds__(128) k_ctx(
    const float* __restrict__ seqs, const float* __restrict__ ets,
    const int* __restrict__ masks)
{
    __shared__ __align__(16) float sM[560];
    __shared__ __align__(16) float sG[20*64];
    __shared__ __align__(16) float s_raw[2][96];
    __shared__ float s_t[2][4][20];
    __shared__ int s_msk[2][12];

    const int tid = threadIdx.x;
    for (int i = tid; i < 560;   i += 128) sM[i] = g_M[i];
    for (int i = tid; i < 20*64; i += 128) sG[i] = g_G[i];
    __syncthreads();

    const int g   = tid >> 6;
    const int o   = tid & 63;
    const int h   = o >> 4;
    const int cl  = o & 15;
    const int hb  = o & 16;                /* segment base within warp */
    const int bar = g + 1;
    const int ggid    = blockIdx.x*2 + g;
    const int ngroups = gridDim.x*2;
    const unsigned FULL = 0xffffffffu;
    const float* Mh = &sM[h*140];

    for (int pr = ggid; pr < NP; pr += ngroups){
        const float* sq = seqs + (size_t)pr*54;
        const float* se = ets  + (size_t)pr*36;
        for (int i = o; i < 90; i += 64) s_raw[g][i] = (i < 54) ? sq[i] : se[i-54];
        if (o < 9) s_msk[g][o] = masks[(size_t)pr*9 + o];
        asm volatile("bar.sync %0, 64;" :: "r"(bar) : "memory");
        const float* rg = s_raw[g];

        float xs[6];
        #pragma unroll
        for (int d = 0; d < 6; d++) xs[d] = rg[24 + d];

        /* t_h[k] = xs~^T M_h : lane cl covers k=cl (and k=16+cl for cl<4) */
        {
            float t1 = Mh[6*20 + cl];
            #pragma unroll
            for (int d = 0; d < 6; d++) t1 += xs[d] * Mh[d*20 + cl];
            s_t[g][h][cl] = t1;
            if (cl < 4){
                int k2 = 16 + cl;
                float t2 = Mh[6*20 + k2];
                #pragma unroll
                for (int d = 0; d < 6; d++) t2 += xs[d] * Mh[d*20 + k2];
                s_t[g][h][k2] = t2;
            }
        }
        __syncwarp();

        /* att for slot n=cl (<9): t.xn~ (one-hot -> direct t[10+n]) */
        float att;
        {
            int n = (cl < 9) ? cl : 8;
            const float* tp = s_t[g][h];
            float v = tp[19] + tp[10 + n];
            #pragma unroll
            for (int k = 0; k < 6; k++) v += tp[k] * rg[n*6 + k];
            #pragma unroll
            for (int j = 0; j < 4; j++) v += tp[6 + j] * rg[54 + n*4 + j];
            att = (cl < 9) ? ((s_msk[g][n] == 0) ? -1e10f : v) : -1e30f;
        }

        /* softmax over 9 inside 16-lane segment */
        float m = att;
        #pragma unroll
        for (int mm = 8; mm >= 1; mm >>= 1) m = fmaxf(m, __shfl_xor_sync(FULL, m, mm));
        float ex = __expf(att - m);
        float ssum = ex;
        #pragma unroll
        for (int mm = 8; mm >= 1; mm >>= 1) ssum += __shfl_xor_sync(FULL, ssum, mm);
        float inv = 1.f / ssum;
        float a[9];
        #pragma unroll
        for (int n = 0; n < 9; n++) a[n] = __shfl_sync(FULL, ex, hb | n) * inv;

        /* xbar[k<10] = sum_n a[n] xn[k]; lane kx=cl computes, then gather */
        float xb = 0.f;
        {
            int kx = (cl < 10) ? cl : 9;
            #pragma unroll
            for (int n = 0; n < 9; n++)
                xb += a[n] * ((kx < 6) ? rg[n*6 + kx] : rg[54 + n*4 + (kx - 6)]);
        }
        float xk[10];
        #pragma unroll
        for (int k = 0; k < 10; k++) xk[k] = __shfl_sync(FULL, xb, hb | k);

        /* ctx[o] = G[19][o] + sum_{k<10} xk G[k][o] + sum_n a_n G[10+n][o] */
        float c = sG[19*64 + o];
        #pragma unroll
        for (int k = 0; k < 10; k++) c += xk[k] * sG[k*64 + o];
        #pragma unroll
        for (int n = 0; n < 9; n++) c += a[n] * sG[(10+n)*64 + o];

        int b = pr / SEQL, s = pr - b*SEQL;            /* time-major for LSTM */
        g_ctx[((size_t)s*BSZ + b)*ATTD + o] = c;
        asm volatile("bar.sync %0, 64;" :: "r"(bar) : "memory");
    }
}

/* ============ kernel 2: xg = ctx @ W_ih^T + (b_ih + b_hh) ================
 * Thread owns 2 gate-cols {j, j+64} x 16 rows; block = 128 thr as 2
 * row-groups of 64, chunk = 32 rows. Per warp-kq: 2 weight LDS.128 (8wf)
 * + 16 broadcast LDS.128 (16wf) per 64 fma2 -> fma-bound.                 */
__global__ void __launch_bounds__(128) k_xg(
    const float* __restrict__ Wih, const float* __restrict__ bih, const float* __restrict__ bhh)
{
    __shared__ __align__(16) float4 s_w4[16*128];  /* [kq][jj] 4-k packed, 32KB */
    __shared__ float s_b[128];
    __shared__ __align__(16) float s_c[32*64];     /* 32 ctx rows, 8KB */
    const int tid = threadIdx.x;
    const int jt  = blockIdx.x & 3;
    const int rb  = blockIdx.x >> 2;               /* 0..184 */
    const int cl  = tid & 63;
    const int rg  = tid >> 6;                      /* row-group 0/1 */
    const int j0  = jt*128 + cl;
    const int j1  = j0 + 64;

    for (int i = tid; i < 16*128; i += 128){
        int kq = i >> 7, jj = i & 127, jg = jt*128 + jj;
        s_w4[i] = make_float4(Wih[jg*64 + 4*kq],   Wih[jg*64 + 4*kq+1],
                              Wih[jg*64 + 4*kq+2], Wih[jg*64 + 4*kq+3]);
    }
    s_b[tid] = bih[jt*128 + tid] + bhh[jt*128 + tid];
    __syncthreads();

    const float b0 = s_b[cl], b1 = s_b[cl + 64];

    for (int r0 = rb*32; r0 < NP; r0 += 185*32){   /* NP % 32 == 0 */
        {   /* stage 32 ctx rows: 512 float4 */
            const float4* src = reinterpret_cast<const float4*>(g_ctx + (size_t)r0*64);
            float4* dst = reinterpret_cast<float4*>(s_c);
            #pragma unroll
            for (int i = 0; i < 4; i++) dst[tid + i*128] = src[tid + i*128];
        }
        __syncthreads();
        ull acc0[16], acc1[16];
        #pragma unroll
        for (int r = 0; r < 16; r++){ acc0[r] = 0ULL; acc1[r] = 0ULL; }
        #pragma unroll 4
        for (int kq = 0; kq < 16; kq++){
            ulonglong2 w0 = *reinterpret_cast<const ulonglong2*>(&s_w4[kq*128 + cl]);
            ulonglong2 w1 = *reinterpret_cast<const ulonglong2*>(&s_w4[kq*128 + cl + 64]);
            #pragma unroll
            for (int r = 0; r < 16; r++){
                ulonglong2 c = *reinterpret_cast<const ulonglong2*>(&s_c[(rg*16 + r)*64 + 4*kq]);
                fma2(acc0[r], w0.x, c.x);
                fma2(acc0[r], w0.y, c.y);
                fma2(acc1[r], w1.x, c.x);
                fma2(acc1[r], w1.y, c.y);
            }
        }
        #pragma unroll
        for (int r = 0; r < 16; r++){
            size_t row = (size_t)(r0 + rg*16 + r);
            g_xg[row*G4 + j0] = hsum2(acc0[r]) + b0;
            g_xg[row*G4 + j1] = hsum2(acc1[r]) + b1;
        }
        __syncthreads();
    }
}

/* ============ kernel 3: recurrent LSTM scan + output GEMM (R7 best) ===== */
__global__ void __launch_bounds__(512, 2) k_lstm(
    const float* __restrict__ Wout, const float* __restrict__ bout, float* __restrict__ outp)
{
    __shared__ __align__(16) float s_h[8*HIDD];    /* 4 KB  */
    __shared__ __align__(16) float s_g[64*HIDD];   /* 32 KB */
    const int tid = threadIdx.x;
    const int c   = tid & 255;                     /* owns cols c and c+256 */
    const int rh  = tid >> 8;                      /* rows 4rh..4rh+3 */
    const int b0  = blockIdx.x * 8;
    for (int i = tid; i < 8*HIDD; i += 512) s_h[i] = 0.f;
    float creg[2] = {0.f, 0.f};
    __syncthreads();

    const ulonglong2* __restrict__ wp = reinterpret_cast<const ulonglong2*>(g_whh4t);

    for (int s = 0; s < SEQL; s++){
        const float* xgp = g_xg + ((size_t)s*BSZ + b0)*G4;
        float xv0[4], xv1[4];
        #pragma unroll
        for (int r = 0; r < 4; r++){
            int row = rh*4 + r;
            xv0[r] = __ldg(&xgp[(size_t)row*G4 + c]);
            xv1[r] = __ldg(&xgp[(size_t)row*G4 + c + 256]);
        }

        ull acc0[4], acc1[4];
        #pragma unroll
        for (int r = 0; r < 4; r++){ acc0[r] = 0ULL; acc1[r] = 0ULL; }

        #pragma unroll 4
        for (int kq = 0; kq < 32; kq++){
            ulonglong2 w0 = __ldg(&wp[kq*G4 + c]);
            ulonglong2 w1 = __ldg(&wp[kq*G4 + 256 + c]);
            ulonglong2 h[4];
            #pragma unroll
            for (int r = 0; r < 4; r++)
                h[r] = *reinterpret_cast<const ulonglong2*>(&s_h[(rh*4 + r)*HIDD + 4*kq]);
            #pragma unroll
            for (int r = 0; r < 4; r++){
                fma2(acc0[r], w0.x, h[r].x);
                fma2(acc0[r], w0.y, h[r].y);
                fma2(acc1[r], w1.x, h[r].x);
                fma2(acc1[r], w1.y, h[r].y);
            }
        }

        #pragma unroll
        for (int r = 0; r < 4; r++){
            int row = rh*4 + r;
            s_g[row*G4 + c]       = hsum2(acc0[r]) + xv0[r];
            s_g[row*G4 + c + 256] = hsum2(acc1[r]) + xv1[r];
        }
        __syncthreads();
        #pragma unroll
        for (int q = 0; q < 2; q++){                        /* 1024 cells / 512 thr */
            int cell = q*512 + tid;
            int r = cell >> 7, j = cell & 127;
            float ig = sigm(s_g[r*G4 + j]);
            float fg = sigm(s_g[r*G4 + 128 + j]);
            float gg = tanhfast(s_g[r*G4 + 256 + j]);
            float og = sigm(s_g[r*G4 + 384 + j]);
            float cc = fg*creg[q] + ig*gg;
            creg[q]  = cc;
            s_h[r*HIDD + j] = og * tanhfast(cc);
        }
        __syncthreads();
    }

    /* out = h_last @ W_out^T + b_out */
    float* s_wo = s_g;
    for (int i = tid; i < 64*HIDD; i += 512){
        int oo = i & 63, jj = i >> 6;
        s_wo[jj*64 + oo] = Wout[oo*HIDD + jj];
    }
    __syncthreads();
    {
        int r = tid >> 6, oo = tid & 63;
        float acc = __ldg(&bout[oo]);
        #pragma unroll 8
        for (int jj = 0; jj < HIDD; jj++) acc += s_wo[jj*64 + oo] * s_h[r*HIDD + jj];
        outp[(size_t)(b0 + r)*64 + oo] = acc;
    }
}

/* ======================================================================== */
extern "C" void kernel_launch(void* const* d_in, const int* in_sizes, int n_in,
                              void* d_out, int out_size)
{
    const float* seqs = (const float*)d_in[0];
    const float* ets  = (const float*)d_in[1];
    const int*   msk  = (const int*)  d_in[2];
    const float* Wfus = (const float*)d_in[3];
    const float* bfus = (const float*)d_in[4];
    const float* Wk   = (const float*)d_in[5];
    const float* bk   = (const float*)d_in[6];
    const float* Wq   = (const float*)d_in[7];
    const float* bq   = (const float*)d_in[8];
    const float* Wv   = (const float*)d_in[9];
    const float* bv   = (const float*)d_in[10];
    const float* Wih  = (const float*)d_in[11];
    const float* Whh  = (const float*)d_in[12];
    const float* bih  = (const float*)d_in[13];
    const float* bhh  = (const float*)d_in[14];
    const float* Wout = (const float*)d_in[15];
    const float* bout = (const float*)d_in[16];
    float* outp = (float*)d_out;

    k_prep<<<24, 128>>>(Wfus, bfus, Wk, bk, Wq, bq, Wv, bv);
    k_pack<<<32, 512>>>(Whh);
    k_ctx <<<592, 128>>>(seqs, ets, msk);
    k_xg  <<<740, 128>>>(Wih, bih, bhh);
    k_lstm<<<256, 512>>>(Wout, bout, outp);
}

// round 12
// speedup vs baseline: 1.5620x; 1.5620x over previous
#include <cuda_runtime.h>

#define BSZ  2048
#define SEQL 50
#define NP   (BSZ*SEQL)      /* 102400 pairs */
#define ATTD 64
#define HIDD 128
#define G4   512             /* 4*HID gates */

typedef unsigned long long ull;

/* ---------------- device scratch (no cudaMalloc allowed) ---------------- */
__device__ float  g_ctx[(size_t)NP * ATTD];        /* [s][b][64]  26 MB  */
__device__ float  g_xg [(size_t)NP * G4];          /* [s][b][512] 210 MB */
__device__ float4 g_whh4t[(HIDD/4) * G4];          /* [kq][col] packed W_hh^T */
__device__ float  g_M[4*7*20];                     /* bilinear att matrices */
__device__ float  g_G[20*64];                      /* folded Wv*Ffus (+bv)  */

/* ---------------- f32x2 helpers ----------------------------------------- */
__device__ __forceinline__ void fma2(ull& d, ull a, ull b){
    asm("fma.rn.f32x2 %0, %1, %2, %0;" : "+l"(d) : "l"(a), "l"(b));
}
__device__ __forceinline__ float2 unpk(ull v){
    float2 r; asm("mov.b64 {%0, %1}, %2;" : "=f"(r.x), "=f"(r.y) : "l"(v)); return r;
}
__device__ __forceinline__ float hsum2(ull v){ float2 f = unpk(v); return f.x + f.y; }
__device__ __forceinline__ float sigm(float x){ return 1.f/(1.f + __expf(-x)); }
__device__ __forceinline__ float tanhfast(float x){ return 1.f - 2.f/(__expf(2.f*x) + 1.f); }

/* ============ kernel P: fold weights into M (4x7x20) and G (20x64) ====== */
__global__ void k_prep(
    const float* __restrict__ Wfus, const float* __restrict__ bfus,
    const float* __restrict__ Wk,   const float* __restrict__ bk,
    const float* __restrict__ Wq,   const float* __restrict__ bq,
    const float* __restrict__ Wv,   const float* __restrict__ bv)
{
    __shared__ float sQ[16*20];
    const int bid = blockIdx.x, tid = threadIdx.x;      /* <<<24,128>>> */
    if (bid < 4){
        int h = bid;
        for (int i = tid; i < 320; i += 128){
            int k = i % 20, d = i / 20, od = h*16 + d;
            float acc = (k == 19) ? bq[od] : 0.f;
            for (int c = 0; c < 64; c++){
                float f = (k < 19) ? Wfus[c*19 + k] : bfus[c];
                acc += Wq[od*64 + c] * f;
            }
            sQ[i] = acc;
        }
        __syncthreads();
        for (int i = tid; i < 140; i += 128){
            int k = i % 20, dp = i / 20;
            float acc = 0.f;
            for (int d = 0; d < 16; d++){
                int o = h*16 + d;
                float wk = (dp < 6) ? Wk[o*6 + dp] : bk[o];
                acc += wk * sQ[d*20 + k];
            }
            g_M[h*140 + dp*20 + k] = 0.25f * acc;
        }
    } else {
        int k = bid - 4;                                /* 0..19 */
        for (int o = tid; o < 64; o += 128){
            float acc = (k == 19) ? bv[o] : 0.f;
            for (int c = 0; c < 64; c++){
                float f = (k < 19) ? Wfus[c*19 + k] : bfus[c];
                acc += Wv[o*64 + c] * f;
            }
            g_G[k*64 + o] = acc;
        }
    }
}

/* ============ kernel 0: transpose+pack W_hh -> [kq][col] float4 ========= */
__global__ void k_pack(const float* __restrict__ Whh){
    int t = threadIdx.x, kq = blockIdx.x;             /* <<<32,512>>> */
    g_whh4t[kq*G4 + t] = make_float4(Whh[t*HIDD + 4*kq],   Whh[t*HIDD + 4*kq+1],
                                     Whh[t*HIDD + 4*kq+2], Whh[t*HIDD + 4*kq+3]);
}

/* ============ kernel 1: attention via precomputed bilinear form (R10) === */
__global__ void __launch_bounds__(128) k_ctx(
    const float* __restrict__ seqs, const float* __restrict__ ets,
    const int* __restrict__ masks)
{
    __shared__ __align__(16) float sM[560];
    __shared__ __align__(16) float sG[20*64];
    __shared__ __align__(16) float s_raw[2][96];
    __shared__ float s_t[2][4][20];
    __shared__ int s_msk[2][12];

    const int tid = threadIdx.x;
    for (int i = tid; i < 560;   i += 128) sM[i] = g_M[i];
    for (int i = tid; i < 20*64; i += 128) sG[i] = g_G[i];
    __syncthreads();

    const int g   = tid >> 6;
    const int o   = tid & 63;
    const int h   = o >> 4;
    const int cl  = o & 15;
    const int hb  = o & 16;                /* segment base within warp */
    const int bar = g + 1;
    const int ggid    = blockIdx.x*2 + g;
    const int ngroups = gridDim.x*2;
    const unsigned FULL = 0xffffffffu;
    const float* Mh = &sM[h*140];

    for (int pr = ggid; pr < NP; pr += ngroups){
        const float* sq = seqs + (size_t)pr*54;
        const float* se = ets  + (size_t)pr*36;
        for (int i = o; i < 90; i += 64) s_raw[g][i] = (i < 54) ? sq[i] : se[i-54];
        if (o < 9) s_msk[g][o] = masks[(size_t)pr*9 + o];
        asm volatile("bar.sync %0, 64;" :: "r"(bar) : "memory");
        const float* rg = s_raw[g];

        float xs[6];
        #pragma unroll
        for (int d = 0; d < 6; d++) xs[d] = rg[24 + d];

        /* t_h[k] = xs~^T M_h : lane cl covers k=cl (and k=16+cl for cl<4) */
        {
            float t1 = Mh[6*20 + cl];
            #pragma unroll
            for (int d = 0; d < 6; d++) t1 += xs[d] * Mh[d*20 + cl];
            s_t[g][h][cl] = t1;
            if (cl < 4){
                int k2 = 16 + cl;
                float t2 = Mh[6*20 + k2];
                #pragma unroll
                for (int d = 0; d < 6; d++) t2 += xs[d] * Mh[d*20 + k2];
                s_t[g][h][k2] = t2;
            }
        }
        __syncwarp();

        /* att for slot n=cl (<9): t.xn~ (one-hot -> direct t[10+n]) */
        float att;
        {
            int n = (cl < 9) ? cl : 8;
            const float* tp = s_t[g][h];
            float v = tp[19] + tp[10 + n];
            #pragma unroll
            for (int k = 0; k < 6; k++) v += tp[k] * rg[n*6 + k];
            #pragma unroll
            for (int j = 0; j < 4; j++) v += tp[6 + j] * rg[54 + n*4 + j];
            att = (cl < 9) ? ((s_msk[g][n] == 0) ? -1e10f : v) : -1e30f;
        }

        /* softmax over 9 inside 16-lane segment */
        float m = att;
        #pragma unroll
        for (int mm = 8; mm >= 1; mm >>= 1) m = fmaxf(m, __shfl_xor_sync(FULL, m, mm));
        float ex = __expf(att - m);
        float ssum = ex;
        #pragma unroll
        for (int mm = 8; mm >= 1; mm >>= 1) ssum += __shfl_xor_sync(FULL, ssum, mm);
        float inv = 1.f / ssum;
        float a[9];
        #pragma unroll
        for (int n = 0; n < 9; n++) a[n] = __shfl_sync(FULL, ex, hb | n) * inv;

        /* xbar[k<10] = sum_n a[n] xn[k]; lane kx=cl computes, then gather */
        float xb = 0.f;
        {
            int kx = (cl < 10) ? cl : 9;
            #pragma unroll
            for (int n = 0; n < 9; n++)
                xb += a[n] * ((kx < 6) ? rg[n*6 + kx] : rg[54 + n*4 + (kx - 6)]);
        }
        float xk[10];
        #pragma unroll
        for (int k = 0; k < 10; k++) xk[k] = __shfl_sync(FULL, xb, hb | k);

        /* ctx[o] = G[19][o] + sum_{k<10} xk G[k][o] + sum_n a_n G[10+n][o] */
        float c = sG[19*64 + o];
        #pragma unroll
        for (int k = 0; k < 10; k++) c += xk[k] * sG[k*64 + o];
        #pragma unroll
        for (int n = 0; n < 9; n++) c += a[n] * sG[(10+n)*64 + o];

        int b = pr / SEQL, s = pr - b*SEQL;            /* time-major for LSTM */
        g_ctx[((size_t)s*BSZ + b)*ATTD + o] = c;
        asm volatile("bar.sync %0, 64;" :: "r"(bar) : "memory");
    }
}

/* ============ kernel 2: xg = ctx @ W_ih^T + (b_ih + b_hh) ================
 * Thread tile = 8 rows x 2 cols {j, j+64} -> 16 f32x2 accumulators (same
 * RF load as R10's 16x1). Per warp-kq: 2 weight LDS.128 (8wf) + 8
 * broadcast LDS.128 (8wf) per 32 fma2 (R10: 20wf). Chunk 16 rows.         */
__global__ void __launch_bounds__(128) k_xg(
    const float* __restrict__ Wih, const float* __restrict__ bih, const float* __restrict__ bhh)
{
    __shared__ __align__(16) float4 s_w4[16*128];  /* [kq][jj] 4-k packed, 32KB */
    __shared__ float s_b[128];
    __shared__ __align__(16) float s_c[16*64];     /* 16 ctx rows, 4KB */
    const int tid = threadIdx.x;
    const int jt  = blockIdx.x & 3;
    const int rb  = blockIdx.x >> 2;               /* 0..221 */
    const int cl  = tid & 63;
    const int rg  = tid >> 6;                      /* row-group 0/1 */
    const int j0  = jt*128 + cl;
    const int j1  = j0 + 64;

    for (int i = tid; i < 16*128; i += 128){
        int kq = i >> 7, jj = i & 127, jg = jt*128 + jj;
        s_w4[i] = make_float4(Wih[jg*64 + 4*kq],   Wih[jg*64 + 4*kq+1],
                              Wih[jg*64 + 4*kq+2], Wih[jg*64 + 4*kq+3]);
    }
    s_b[tid] = bih[jt*128 + tid] + bhh[jt*128 + tid];
    __syncthreads();

    const float b0 = s_b[cl], b1 = s_b[cl + 64];

    for (int r0 = rb*16; r0 < NP; r0 += 222*16){   /* NP % 16 == 0 */
        for (int i = tid; i < 16*64; i += 128) s_c[i] = g_ctx[(size_t)r0*64 + i];
        __syncthreads();
        ull acc0[8], acc1[8];
        #pragma unroll
        for (int r = 0; r < 8; r++){ acc0[r] = 0ULL; acc1[r] = 0ULL; }
        #pragma unroll 4
        for (int kq = 0; kq < 16; kq++){
            ulonglong2 w0 = *reinterpret_cast<const ulonglong2*>(&s_w4[kq*128 + cl]);
            ulonglong2 w1 = *reinterpret_cast<const ulonglong2*>(&s_w4[kq*128 + cl + 64]);
            #pragma unroll
            for (int r = 0; r < 8; r++){
                ulonglong2 c = *reinterpret_cast<const ulonglong2*>(&s_c[(rg*8 + r)*64 + 4*kq]);
                fma2(acc0[r], w0.x, c.x);
                fma2(acc0[r], w0.y, c.y);
                fma2(acc1[r], w1.x, c.x);
                fma2(acc1[r], w1.y, c.y);
            }
        }
        #pragma unroll
        for (int r = 0; r < 8; r++){
            size_t row = (size_t)(r0 + rg*8 + r);
            g_xg[row*G4 + j0] = hsum2(acc0[r]) + b0;
            g_xg[row*G4 + j1] = hsum2(acc1[r]) + b1;
        }
        __syncthreads();
    }
}

/* ============ kernel 3: recurrent LSTM scan + output GEMM (R7 best) ===== */
__global__ void __launch_bounds__(512, 2) k_lstm(
    const float* __restrict__ Wout, const float* __restrict__ bout, float* __restrict__ outp)
{
    __shared__ __align__(16) float s_h[8*HIDD];    /* 4 KB  */
    __shared__ __align__(16) float s_g[64*HIDD];   /* 32 KB */
    const int tid = threadIdx.x;
    const int c   = tid & 255;                     /* owns cols c and c+256 */
    const int rh  = tid >> 8;                      /* rows 4rh..4rh+3 */
    const int b0  = blockIdx.x * 8;
    for (int i = tid; i < 8*HIDD; i += 512) s_h[i] = 0.f;
    float creg[2] = {0.f, 0.f};
    __syncthreads();

    const ulonglong2* __restrict__ wp = reinterpret_cast<const ulonglong2*>(g_whh4t);

    for (int s = 0; s < SEQL; s++){
        const float* xgp = g_xg + ((size_t)s*BSZ + b0)*G4;
        float xv0[4], xv1[4];
        #pragma unroll
        for (int r = 0; r < 4; r++){
            int row = rh*4 + r;
            xv0[r] = __ldg(&xgp[(size_t)row*G4 + c]);
            xv1[r] = __ldg(&xgp[(size_t)row*G4 + c + 256]);
        }

        ull acc0[4], acc1[4];
        #pragma unroll
        for (int r = 0; r < 4; r++){ acc0[r] = 0ULL; acc1[r] = 0ULL; }

        #pragma unroll 4
        for (int kq = 0; kq < 32; kq++){
            ulonglong2 w0 = __ldg(&wp[kq*G4 + c]);
            ulonglong2 w1 = __ldg(&wp[kq*G4 + 256 + c]);
            ulonglong2 h[4];
            #pragma unroll
            for (int r = 0; r < 4; r++)
                h[r] = *reinterpret_cast<const ulonglong2*>(&s_h[(rh*4 + r)*HIDD + 4*kq]);
            #pragma unroll
            for (int r = 0; r < 4; r++){
                fma2(acc0[r], w0.x, h[r].x);
                fma2(acc0[r], w0.y, h[r].y);
                fma2(acc1[r], w1.x, h[r].x);
                fma2(acc1[r], w1.y, h[r].y);
            }
        }

        #pragma unroll
        for (int r = 0; r < 4; r++){
            int row = rh*4 + r;
            s_g[row*G4 + c]       = hsum2(acc0[r]) + xv0[r];
            s_g[row*G4 + c + 256] = hsum2(acc1[r]) + xv1[r];
        }
        __syncthreads();
        #pragma unroll
        for (int q = 0; q < 2; q++){                        /* 1024 cells / 512 thr */
            int cell = q*512 + tid;
            int r = cell >> 7, j = cell & 127;
            float ig = sigm(s_g[r*G4 + j]);
            float fg = sigm(s_g[r*G4 + 128 + j]);
            float gg = tanhfast(s_g[r*G4 + 256 + j]);
            float og = sigm(s_g[r*G4 + 384 + j]);
            float cc = fg*creg[q] + ig*gg;
            creg[q]  = cc;
            s_h[r*HIDD + j] = og * tanhfast(cc);
        }
        __syncthreads();
    }

    /* out = h_last @ W_out^T + b_out */
    float* s_wo = s_g;
    for (int i = tid; i < 64*HIDD; i += 512){
        int oo = i & 63, jj = i >> 6;
        s_wo[jj*64 + oo] = Wout[oo*HIDD + jj];
    }
    __syncthreads();
    {
        int r = tid >> 6, oo = tid & 63;
        float acc = __ldg(&bout[oo]);
        #pragma unroll 8
        for (int jj = 0; jj < HIDD; jj++) acc += s_wo[jj*64 + oo] * s_h[r*HIDD + jj];
        outp[(size_t)(b0 + r)*64 + oo] = acc;
    }
}

/* ======================================================================== */
extern "C" void kernel_launch(void* const* d_in, const int* in_sizes, int n_in,
                              void* d_out, int out_size)
{
    const float* seqs = (const float*)d_in[0];
    const float* ets  = (const float*)d_in[1];
    const int*   msk  = (const int*)  d_in[2];
    const float* Wfus = (const float*)d_in[3];
    const float* bfus = (const float*)d_in[4];
    const float* Wk   = (const float*)d_in[5];
    const float* bk   = (const float*)d_in[6];
    const float* Wq   = (const float*)d_in[7];
    const float* bq   = (const float*)d_in[8];
    const float* Wv   = (const float*)d_in[9];
    const float* bv   = (const float*)d_in[10];
    const float* Wih  = (const float*)d_in[11];
    const float* Whh  = (const float*)d_in[12];
    const float* bih  = (const float*)d_in[13];
    const float* bhh  = (const float*)d_in[14];
    const float* Wout = (const float*)d_in[15];
    const float* bout = (const float*)d_in[16];
    float* outp = (float*)d_out;

    k_prep<<<24, 128>>>(Wfus, bfus, Wk, bk, Wq, bq, Wv, bv);
    k_pack<<<32, 512>>>(Whh);
    k_ctx <<<592, 128>>>(seqs, ets, msk);
    k_xg  <<<888, 128>>>(Wih, bih, bhh);
    k_lstm<<<256, 512>>>(Wout, bout, outp);
}

// round 13
// speedup vs baseline: 1.5747x; 1.0081x over previous
#include <cuda_runtime.h>
#include <cuda_fp16.h>

#define BSZ  2048
#define SEQL 50
#define NP   (BSZ*SEQL)      /* 102400 pairs */
#define ATTD 64
#define HIDD 128
#define G4   512             /* 4*HID gates */

typedef unsigned long long ull;

/* ---------------- device scratch (no cudaMalloc allowed) ---------------- */
__device__ float  g_ctx[(size_t)NP * ATTD];        /* [s][b][64]  26 MB  */
__device__ float  g_xg [(size_t)NP * G4];          /* [s][b][512] 210 MB */
__device__ uint2  g_whhh[(HIDD/4) * G4];           /* [kq][col] fp16x4 W_hh^T */
__device__ float  g_M[4*7*20];                     /* bilinear att matrices */
__device__ float  g_G[20*64];                      /* folded Wv*Ffus (+bv)  */

/* ---------------- f32x2 helpers ----------------------------------------- */
__device__ __forceinline__ void fma2(ull& d, ull a, ull b){
    asm("fma.rn.f32x2 %0, %1, %2, %0;" : "+l"(d) : "l"(a), "l"(b));
}
__device__ __forceinline__ float2 unpk(ull v){
    float2 r; asm("mov.b64 {%0, %1}, %2;" : "=f"(r.x), "=f"(r.y) : "l"(v)); return r;
}
__device__ __forceinline__ float hsum2(ull v){ float2 f = unpk(v); return f.x + f.y; }
__device__ __forceinline__ ull h2f2(unsigned u){        /* half2 -> packed f32x2 */
    __half2 h = *reinterpret_cast<__half2*>(&u);
    float2 f = __half22float2(h);
    ull r; asm("mov.b64 %0, {%1, %2};" : "=l"(r) : "f"(f.x), "f"(f.y));
    return r;
}
__device__ __forceinline__ float sigm(float x){ return 1.f/(1.f + __expf(-x)); }
__device__ __forceinline__ float tanhfast(float x){ return 1.f - 2.f/(__expf(2.f*x) + 1.f); }

/* ============ kernel P: fold weights into M (4x7x20) and G (20x64) ====== */
__global__ void k_prep(
    const float* __restrict__ Wfus, const float* __restrict__ bfus,
    const float* __restrict__ Wk,   const float* __restrict__ bk,
    const float* __restrict__ Wq,   const float* __restrict__ bq,
    const float* __restrict__ Wv,   const float* __restrict__ bv)
{
    __shared__ float sQ[16*20];
    const int bid = blockIdx.x, tid = threadIdx.x;      /* <<<24,128>>> */
    if (bid < 4){
        int h = bid;
        for (int i = tid; i < 320; i += 128){
            int k = i % 20, d = i / 20, od = h*16 + d;
            float acc = (k == 19) ? bq[od] : 0.f;
            for (int c = 0; c < 64; c++){
                float f = (k < 19) ? Wfus[c*19 + k] : bfus[c];
                acc += Wq[od*64 + c] * f;
            }
            sQ[i] = acc;
        }
        __syncthreads();
        for (int i = tid; i < 140; i += 128){
            int k = i % 20, dp = i / 20;
            float acc = 0.f;
            for (int d = 0; d < 16; d++){
                int o = h*16 + d;
                float wk = (dp < 6) ? Wk[o*6 + dp] : bk[o];
                acc += wk * sQ[d*20 + k];
            }
            g_M[h*140 + dp*20 + k] = 0.25f * acc;
        }
    } else {
        int k = bid - 4;                                /* 0..19 */
        for (int o = tid; o < 64; o += 128){
            float acc = (k == 19) ? bv[o] : 0.f;
            for (int c = 0; c < 64; c++){
                float f = (k < 19) ? Wfus[c*19 + k] : bfus[c];
                acc += Wv[o*64 + c] * f;
            }
            g_G[k*64 + o] = acc;
        }
    }
}

/* ============ kernel 0: pack W_hh^T -> [kq][col] fp16x4 ================= */
__global__ void k_pack(const float* __restrict__ Whh){
    int t = threadIdx.x, kq = blockIdx.x;             /* <<<32,512>>> */
    __half2 a = __floats2half2_rn(Whh[t*HIDD + 4*kq],   Whh[t*HIDD + 4*kq+1]);
    __half2 b = __floats2half2_rn(Whh[t*HIDD + 4*kq+2], Whh[t*HIDD + 4*kq+3]);
    uint2 u;
    u.x = *reinterpret_cast<unsigned*>(&a);
    u.y = *reinterpret_cast<unsigned*>(&b);
    g_whhh[kq*G4 + t] = u;
}

/* ============ kernel 1: attention via precomputed bilinear form (R10) === */
__global__ void __launch_bounds__(128) k_ctx(
    const float* __restrict__ seqs, const float* __restrict__ ets,
    const int* __restrict__ masks)
{
    __shared__ __align__(16) float sM[560];
    __shared__ __align__(16) float sG[20*64];
    __shared__ __align__(16) float s_raw[2][96];
    __shared__ float s_t[2][4][20];
    __shared__ int s_msk[2][12];

    const int tid = threadIdx.x;
    for (int i = tid; i < 560;   i += 128) sM[i] = g_M[i];
    for (int i = tid; i < 20*64; i += 128) sG[i] = g_G[i];
    __syncthreads();

    const int g   = tid >> 6;
    const int o   = tid & 63;
    const int h   = o >> 4;
    const int cl  = o & 15;
    const int hb  = o & 16;                /* segment base within warp */
    const int bar = g + 1;
    const int ggid    = blockIdx.x*2 + g;
    const int ngroups = gridDim.x*2;
    const unsigned FULL = 0xffffffffu;
    const float* Mh = &sM[h*140];

    for (int pr = ggid; pr < NP; pr += ngroups){
        const float* sq = seqs + (size_t)pr*54;
        const float* se = ets  + (size_t)pr*36;
        for (int i = o; i < 90; i += 64) s_raw[g][i] = (i < 54) ? sq[i] : se[i-54];
        if (o < 9) s_msk[g][o] = masks[(size_t)pr*9 + o];
        asm volatile("bar.sync %0, 64;" :: "r"(bar) : "memory");
        const float* rg = s_raw[g];

        float xs[6];
        #pragma unroll
        for (int d = 0; d < 6; d++) xs[d] = rg[24 + d];

        /* t_h[k] = xs~^T M_h : lane cl covers k=cl (and k=16+cl for cl<4) */
        {
            float t1 = Mh[6*20 + cl];
            #pragma unroll
            for (int d = 0; d < 6; d++) t1 += xs[d] * Mh[d*20 + cl];
            s_t[g][h][cl] = t1;
            if (cl < 4){
                int k2 = 16 + cl;
                float t2 = Mh[6*20 + k2];
                #pragma unroll
                for (int d = 0; d < 6; d++) t2 += xs[d] * Mh[d*20 + k2];
                s_t[g][h][k2] = t2;
            }
        }
        __syncwarp();

        /* att for slot n=cl (<9): t.xn~ (one-hot -> direct t[10+n]) */
        float att;
        {
            int n = (cl < 9) ? cl : 8;
            const float* tp = s_t[g][h];
            float v = tp[19] + tp[10 + n];
            #pragma unroll
            for (int k = 0; k < 6; k++) v += tp[k] * rg[n*6 + k];
            #pragma unroll
            for (int j = 0; j < 4; j++) v += tp[6 + j] * rg[54 + n*4 + j];
            att = (cl < 9) ? ((s_msk[g][n] == 0) ? -1e10f : v) : -1e30f;
        }

        /* softmax over 9 inside 16-lane segment */
        float m = att;
        #pragma unroll
        for (int mm = 8; mm >= 1; mm >>= 1) m = fmaxf(m, __shfl_xor_sync(FULL, m, mm));
        float ex = __expf(att - m);
        float ssum = ex;
        #pragma unroll
        for (int mm = 8; mm >= 1; mm >>= 1) ssum += __shfl_xor_sync(FULL, ssum, mm);
        float inv = 1.f / ssum;
        float a[9];
        #pragma unroll
        for (int n = 0; n < 9; n++) a[n] = __shfl_sync(FULL, ex, hb | n) * inv;

        /* xbar[k<10] = sum_n a[n] xn[k]; lane kx=cl computes, then gather */
        float xb = 0.f;
        {
            int kx = (cl < 10) ? cl : 9;
            #pragma unroll
            for (int n = 0; n < 9; n++)
                xb += a[n] * ((kx < 6) ? rg[n*6 + kx] : rg[54 + n*4 + (kx - 6)]);
        }
        float xk[10];
        #pragma unroll
        for (int k = 0; k < 10; k++) xk[k] = __shfl_sync(FULL, xb, hb | k);

        /* ctx[o] = G[19][o] + sum_{k<10} xk G[k][o] + sum_n a_n G[10+n][o] */
        float c = sG[19*64 + o];
        #pragma unroll
        for (int k = 0; k < 10; k++) c += xk[k] * sG[k*64 + o];
        #pragma unroll
        for (int n = 0; n < 9; n++) c += a[n] * sG[(10+n)*64 + o];

        int b = pr / SEQL, s = pr - b*SEQL;            /* time-major for LSTM */
        g_ctx[((size_t)s*BSZ + b)*ATTD + o] = c;
        asm volatile("bar.sync %0, 64;" :: "r"(bar) : "memory");
    }
}

/* ============ kernel 2: xg = ctx @ W_ih^T + (b_ih + b_hh) (R12) ========= */
__global__ void __launch_bounds__(128) k_xg(
    const float* __restrict__ Wih, const float* __restrict__ bih, const float* __restrict__ bhh)
{
    __shared__ __align__(16) float4 s_w4[16*128];  /* [kq][jj] 4-k packed, 32KB */
    __shared__ float s_b[128];
    __shared__ __align__(16) float s_c[16*64];     /* 16 ctx rows, 4KB */
    const int tid = threadIdx.x;
    const int jt  = blockIdx.x & 3;
    const int rb  = blockIdx.x >> 2;               /* 0..221 */
    const int cl  = tid & 63;
    const int rg  = tid >> 6;                      /* row-group 0/1 */
    const int j0  = jt*128 + cl;
    const int j1  = j0 + 64;

    for (int i = tid; i < 16*128; i += 128){
        int kq = i >> 7, jj = i & 127, jg = jt*128 + jj;
        s_w4[i] = make_float4(Wih[jg*64 + 4*kq],   Wih[jg*64 + 4*kq+1],
                              Wih[jg*64 + 4*kq+2], Wih[jg*64 + 4*kq+3]);
    }
    s_b[tid] = bih[jt*128 + tid] + bhh[jt*128 + tid];
    __syncthreads();

    const float b0 = s_b[cl], b1 = s_b[cl + 64];

    for (int r0 = rb*16; r0 < NP; r0 += 222*16){   /* NP % 16 == 0 */
        for (int i = tid; i < 16*64; i += 128) s_c[i] = g_ctx[(size_t)r0*64 + i];
        __syncthreads();
        ull acc0[8], acc1[8];
        #pragma unroll
        for (int r = 0; r < 8; r++){ acc0[r] = 0ULL; acc1[r] = 0ULL; }
        #pragma unroll 4
        for (int kq = 0; kq < 16; kq++){
            ulonglong2 w0 = *reinterpret_cast<const ulonglong2*>(&s_w4[kq*128 + cl]);
            ulonglong2 w1 = *reinterpret_cast<const ulonglong2*>(&s_w4[kq*128 + cl + 64]);
            #pragma unroll
            for (int r = 0; r < 8; r++){
                ulonglong2 c = *reinterpret_cast<const ulonglong2*>(&s_c[(rg*8 + r)*64 + 4*kq]);
                fma2(acc0[r], w0.x, c.x);
                fma2(acc0[r], w0.y, c.y);
                fma2(acc1[r], w1.x, c.x);
                fma2(acc1[r], w1.y, c.y);
            }
        }
        #pragma unroll
        for (int r = 0; r < 8; r++){
            size_t row = (size_t)(r0 + rg*8 + r);
            g_xg[row*G4 + j0] = hsum2(acc0[r]) + b0;
            g_xg[row*G4 + j1] = hsum2(acc1[r]) + b1;
        }
        __syncthreads();
    }
}

/* ============ kernel 3: recurrent LSTM scan + output GEMM ================
 * R7 shape (512 thr, 2/SM, 8 rows, thread = 4 rows x 2 cols) but weights
 * stream as fp16x4 (LDG.64): weight L1 wavefronts halved vs fp32.         */
__global__ void __launch_bounds__(512, 2) k_lstm(
    const float* __restrict__ Wout, const float* __restrict__ bout, float* __restrict__ outp)
{
    __shared__ __align__(16) float s_h[8*HIDD];    /* 4 KB  */
    __shared__ __align__(16) float s_g[64*HIDD];   /* 32 KB */
    const int tid = threadIdx.x;
    const int c   = tid & 255;                     /* owns cols c and c+256 */
    const int rh  = tid >> 8;                      /* rows 4rh..4rh+3 */
    const int b0  = blockIdx.x * 8;
    for (int i = tid; i < 8*HIDD; i += 512) s_h[i] = 0.f;
    float creg[2] = {0.f, 0.f};
    __syncthreads();

    const uint2* __restrict__ wp = g_whhh;

    for (int s = 0; s < SEQL; s++){
        const float* xgp = g_xg + ((size_t)s*BSZ + b0)*G4;
        float xv0[4], xv1[4];
        #pragma unroll
        for (int r = 0; r < 4; r++){
            int row = rh*4 + r;
            xv0[r] = __ldg(&xgp[(size_t)row*G4 + c]);
            xv1[r] = __ldg(&xgp[(size_t)row*G4 + c + 256]);
        }

        ull acc0[4], acc1[4];
        #pragma unroll
        for (int r = 0; r < 4; r++){ acc0[r] = 0ULL; acc1[r] = 0ULL; }

        #pragma unroll 4
        for (int kq = 0; kq < 32; kq++){
            uint2 u0 = __ldg(&wp[kq*G4 + c]);               /* LDG.64 coalesced */
            uint2 u1 = __ldg(&wp[kq*G4 + 256 + c]);
            ull w0a = h2f2(u0.x), w0b = h2f2(u0.y);
            ull w1a = h2f2(u1.x), w1b = h2f2(u1.y);
            ulonglong2 h[4];
            #pragma unroll
            for (int r = 0; r < 4; r++)
                h[r] = *reinterpret_cast<const ulonglong2*>(&s_h[(rh*4 + r)*HIDD + 4*kq]);
            #pragma unroll
            for (int r = 0; r < 4; r++){
                fma2(acc0[r], w0a, h[r].x);
                fma2(acc0[r], w0b, h[r].y);
                fma2(acc1[r], w1a, h[r].x);
                fma2(acc1[r], w1b, h[r].y);
            }
        }

        #pragma unroll
        for (int r = 0; r < 4; r++){
            int row = rh*4 + r;
            s_g[row*G4 + c]       = hsum2(acc0[r]) + xv0[r];
            s_g[row*G4 + c + 256] = hsum2(acc1[r]) + xv1[r];
        }
        __syncthreads();
        #pragma unroll
        for (int q = 0; q < 2; q++){                        /* 1024 cells / 512 thr */
            int cell = q*512 + tid;
            int r = cell >> 7, j = cell & 127;
            float ig = sigm(s_g[r*G4 + j]);
            float fg = sigm(s_g[r*G4 + 128 + j]);
            float gg = tanhfast(s_g[r*G4 + 256 + j]);
            float og = sigm(s_g[r*G4 + 384 + j]);
            float cc = fg*creg[q] + ig*gg;
            creg[q]  = cc;
            s_h[r*HIDD + j] = og * tanhfast(cc);
        }
        __syncthreads();
    }

    /* out = h_last @ W_out^T + b_out */
    float* s_wo = s_g;
    for (int i = tid; i < 64*HIDD; i += 512){
        int oo = i & 63, jj = i >> 6;
        s_wo[jj*64 + oo] = Wout[oo*HIDD + jj];
    }
    __syncthreads();
    {
        int r = tid >> 6, oo = tid & 63;
        float acc = __ldg(&bout[oo]);
        #pragma unroll 8
        for (int jj = 0; jj < HIDD; jj++) acc += s_wo[jj*64 + oo] * s_h[r*HIDD + jj];
        outp[(size_t)(b0 + r)*64 + oo] = acc;
    }
}

/* ======================================================================== */
extern "C" void kernel_launch(void* const* d_in, const int* in_sizes, int n_in,
                              void* d_out, int out_size)
{
    const float* seqs = (const float*)d_in[0];
    const float* ets  = (const float*)d_in[1];
    const int*   msk  = (const int*)  d_in[2];
    const float* Wfus = (const float*)d_in[3];
    const float* bfus = (const float*)d_in[4];
    const float* Wk   = (const float*)d_in[5];
    const float* bk   = (const float*)d_in[6];
    const float* Wq   = (const float*)d_in[7];
    const float* bq   = (const float*)d_in[8];
    const float* Wv   = (const float*)d_in[9];
    const float* bv   = (const float*)d_in[10];
    const float* Wih  = (const float*)d_in[11];
    const float* Whh  = (const float*)d_in[12];
    const float* bih  = (const float*)d_in[13];
    const float* bhh  = (const float*)d_in[14];
    const float* Wout = (const float*)d_in[15];
    const float* bout = (const float*)d_in[16];
    float* outp = (float*)d_out;

    k_prep<<<24, 128>>>(Wfus, bfus, Wk, bk, Wq, bq, Wv, bv);
    k_pack<<<32, 512>>>(Whh);
    k_ctx <<<592, 128>>>(seqs, ets, msk);
    k_xg  <<<888, 128>>>(Wih, bih, bhh);
    k_lstm<<<256, 512>>>(Wout, bout, outp);
}

// round 14
// speedup vs baseline: 1.6221x; 1.0301x over previous
#include <cuda_runtime.h>
#include <cuda_fp16.h>

#define BSZ  2048
#define SEQL 50
#define NP   (BSZ*SEQL)      /* 102400 pairs */
#define ATTD 64
#define HIDD 128
#define G4   512             /* 4*HID gates */

typedef unsigned long long ull;

/* ---------------- device scratch (no cudaMalloc allowed) ---------------- */
__device__ float  g_ctx[(size_t)NP * ATTD];        /* [s][b][64]  26 MB  */
__device__ float  g_xg [(size_t)NP * G4];          /* [s][b][512] 210 MB */
__device__ uint2  g_whhh[(HIDD/4) * G4];           /* [kq][col] fp16x4 W_hh^T */
__device__ float  g_M[4*7*20];                     /* bilinear att matrices */
__device__ float  g_G[20*64];                      /* folded Wv*Ffus (+bv)  */

/* ---------------- helpers ----------------------------------------------- */
__device__ __forceinline__ void fma2(ull& d, ull a, ull b){
    asm("fma.rn.f32x2 %0, %1, %2, %0;" : "+l"(d) : "l"(a), "l"(b));
}
__device__ __forceinline__ float2 unpk(ull v){
    float2 r; asm("mov.b64 {%0, %1}, %2;" : "=f"(r.x), "=f"(r.y) : "l"(v)); return r;
}
__device__ __forceinline__ float hsum2(ull v){ float2 f = unpk(v); return f.x + f.y; }
__device__ __forceinline__ ull h2f2(unsigned u){        /* half2 -> packed f32x2 */
    __half2 h = *reinterpret_cast<__half2*>(&u);
    float2 f = __half22float2(h);
    ull r; asm("mov.b64 %0, {%1, %2};" : "=l"(r) : "f"(f.x), "f"(f.y));
    return r;
}
__device__ __forceinline__ float tanha(float x){        /* HW tanh, 1 XU op */
    float r; asm("tanh.approx.f32 %0, %1;" : "=f"(r) : "f"(x)); return r;
}
__device__ __forceinline__ float sigma(float x){        /* sigmoid via tanh */
    return fmaf(0.5f, tanha(0.5f*x), 0.5f);
}
__device__ __forceinline__ float sigm(float x){ return 1.f/(1.f + __expf(-x)); }

/* ============ kernel P: fold weights into M (4x7x20) and G (20x64) ====== */
__global__ void k_prep(
    const float* __restrict__ Wfus, const float* __restrict__ bfus,
    const float* __restrict__ Wk,   const float* __restrict__ bk,
    const float* __restrict__ Wq,   const float* __restrict__ bq,
    const float* __restrict__ Wv,   const float* __restrict__ bv)
{
    __shared__ float sQ[16*20];
    const int bid = blockIdx.x, tid = threadIdx.x;      /* <<<24,128>>> */
    if (bid < 4){
        int h = bid;
        for (int i = tid; i < 320; i += 128){
            int k = i % 20, d = i / 20, od = h*16 + d;
            float acc = (k == 19) ? bq[od] : 0.f;
            for (int c = 0; c < 64; c++){
                float f = (k < 19) ? Wfus[c*19 + k] : bfus[c];
                acc += Wq[od*64 + c] * f;
            }
            sQ[i] = acc;
        }
        __syncthreads();
        for (int i = tid; i < 140; i += 128){
            int k = i % 20, dp = i / 20;
            float acc = 0.f;
            for (int d = 0; d < 16; d++){
                int o = h*16 + d;
                float wk = (dp < 6) ? Wk[o*6 + dp] : bk[o];
                acc += wk * sQ[d*20 + k];
            }
            g_M[h*140 + dp*20 + k] = 0.25f * acc;
        }
    } else {
        int k = bid - 4;                                /* 0..19 */
        for (int o = tid; o < 64; o += 128){
            float acc = (k == 19) ? bv[o] : 0.f;
            for (int c = 0; c < 64; c++){
                float f = (k < 19) ? Wfus[c*19 + k] : bfus[c];
                acc += Wv[o*64 + c] * f;
            }
            g_G[k*64 + o] = acc;
        }
    }
}

/* ============ kernel 0: pack W_hh^T -> [kq][col] fp16x4 ================= */
__global__ void k_pack(const float* __restrict__ Whh){
    int t = threadIdx.x, kq = blockIdx.x;             /* <<<32,512>>> */
    __half2 a = __floats2half2_rn(Whh[t*HIDD + 4*kq],   Whh[t*HIDD + 4*kq+1]);
    __half2 b = __floats2half2_rn(Whh[t*HIDD + 4*kq+2], Whh[t*HIDD + 4*kq+3]);
    uint2 u;
    u.x = *reinterpret_cast<unsigned*>(&a);
    u.y = *reinterpret_cast<unsigned*>(&b);
    g_whhh[kq*G4 + t] = u;
}

/* ============ kernel 1: attention via precomputed bilinear form (R10) === */
__global__ void __launch_bounds__(128) k_ctx(
    const float* __restrict__ seqs, const float* __restrict__ ets,
    const int* __restrict__ masks)
{
    __shared__ __align__(16) float sM[560];
    __shared__ __align__(16) float sG[20*64];
    __shared__ __align__(16) float s_raw[2][96];
    __shared__ float s_t[2][4][20];
    __shared__ int s_msk[2][12];

    const int tid = threadIdx.x;
    for (int i = tid; i < 560;   i += 128) sM[i] = g_M[i];
    for (int i = tid; i < 20*64; i += 128) sG[i] = g_G[i];
    __syncthreads();

    const int g   = tid >> 6;
    const int o   = tid & 63;
    const int h   = o >> 4;
    const int cl  = o & 15;
    const int hb  = o & 16;                /* segment base within warp */
    const int bar = g + 1;
    const int ggid    = blockIdx.x*2 + g;
    const int ngroups = gridDim.x*2;
    const unsigned FULL = 0xffffffffu;
    const float* Mh = &sM[h*140];

    for (int pr = ggid; pr < NP; pr += ngroups){
        const float* sq = seqs + (size_t)pr*54;
        const float* se = ets  + (size_t)pr*36;
        for (int i = o; i < 90; i += 64) s_raw[g][i] = (i < 54) ? sq[i] : se[i-54];
        if (o < 9) s_msk[g][o] = masks[(size_t)pr*9 + o];
        asm volatile("bar.sync %0, 64;" :: "r"(bar) : "memory");
        const float* rg = s_raw[g];

        float xs[6];
        #pragma unroll
        for (int d = 0; d < 6; d++) xs[d] = rg[24 + d];

        /* t_h[k] = xs~^T M_h : lane cl covers k=cl (and k=16+cl for cl<4) */
        {
            float t1 = Mh[6*20 + cl];
            #pragma unroll
            for (int d = 0; d < 6; d++) t1 += xs[d] * Mh[d*20 + cl];
            s_t[g][h][cl] = t1;
            if (cl < 4){
                int k2 = 16 + cl;
                float t2 = Mh[6*20 + k2];
                #pragma unroll
                for (int d = 0; d < 6; d++) t2 += xs[d] * Mh[d*20 + k2];
                s_t[g][h][k2] = t2;
            }
        }
        __syncwarp();

        /* att for slot n=cl (<9): t.xn~ (one-hot -> direct t[10+n]) */
        float att;
        {
            int n = (cl < 9) ? cl : 8;
            const float* tp = s_t[g][h];
            float v = tp[19] + tp[10 + n];
            #pragma unroll
            for (int k = 0; k < 6; k++) v += tp[k] * rg[n*6 + k];
            #pragma unroll
            for (int j = 0; j < 4; j++) v += tp[6 + j] * rg[54 + n*4 + j];
            att = (cl < 9) ? ((s_msk[g][n] == 0) ? -1e10f : v) : -1e30f;
        }

        /* softmax over 9 inside 16-lane segment */
        float m = att;
        #pragma unroll
        for (int mm = 8; mm >= 1; mm >>= 1) m = fmaxf(m, __shfl_xor_sync(FULL, m, mm));
        float ex = __expf(att - m);
        float ssum = ex;
        #pragma unroll
        for (int mm = 8; mm >= 1; mm >>= 1) ssum += __shfl_xor_sync(FULL, ssum, mm);
        float inv = 1.f / ssum;
        float a[9];
        #pragma unroll
        for (int n = 0; n < 9; n++) a[n] = __shfl_sync(FULL, ex, hb | n) * inv;

        /* xbar[k<10] = sum_n a[n] xn[k]; lane kx=cl computes, then gather */
        float xb = 0.f;
        {
            int kx = (cl < 10) ? cl : 9;
            #pragma unroll
            for (int n = 0; n < 9; n++)
                xb += a[n] * ((kx < 6) ? rg[n*6 + kx] : rg[54 + n*4 + (kx - 6)]);
        }
        float xk[10];
        #pragma unroll
        for (int k = 0; k < 10; k++) xk[k] = __shfl_sync(FULL, xb, hb | k);

        /* ctx[o] = G[19][o] + sum_{k<10} xk G[k][o] + sum_n a_n G[10+n][o] */
        float c = sG[19*64 + o];
        #pragma unroll
        for (int k = 0; k < 10; k++) c += xk[k] * sG[k*64 + o];
        #pragma unroll
        for (int n = 0; n < 9; n++) c += a[n] * sG[(10+n)*64 + o];

        int b = pr / SEQL, s = pr - b*SEQL;            /* time-major for LSTM */
        g_ctx[((size_t)s*BSZ + b)*ATTD + o] = c;
        asm volatile("bar.sync %0, 64;" :: "r"(bar) : "memory");
    }
}

/* ============ kernel 2: xg = ctx @ W_ih^T + (b_ih + b_hh) (R12) ========= */
__global__ void __launch_bounds__(128) k_xg(
    const float* __restrict__ Wih, const float* __restrict__ bih, const float* __restrict__ bhh)
{
    __shared__ __align__(16) float4 s_w4[16*128];  /* [kq][jj] 4-k packed, 32KB */
    __shared__ float s_b[128];
    __shared__ __align__(16) float s_c[16*64];     /* 16 ctx rows, 4KB */
    const int tid = threadIdx.x;
    const int jt  = blockIdx.x & 3;
    const int rb  = blockIdx.x >> 2;               /* 0..221 */
    const int cl  = tid & 63;
    const int rg  = tid >> 6;                      /* row-group 0/1 */
    const int j0  = jt*128 + cl;
    const int j1  = j0 + 64;

    for (int i = tid; i < 16*128; i += 128){
        int kq = i >> 7, jj = i & 127, jg = jt*128 + jj;
        s_w4[i] = make_float4(Wih[jg*64 + 4*kq],   Wih[jg*64 + 4*kq+1],
                              Wih[jg*64 + 4*kq+2], Wih[jg*64 + 4*kq+3]);
    }
    s_b[tid] = bih[jt*128 + tid] + bhh[jt*128 + tid];
    __syncthreads();

    const float b0 = s_b[cl], b1 = s_b[cl + 64];

    for (int r0 = rb*16; r0 < NP; r0 += 222*16){   /* NP % 16 == 0 */
        for (int i = tid; i < 16*64; i += 128) s_c[i] = g_ctx[(size_t)r0*64 + i];
        __syncthreads();
        ull acc0[8], acc1[8];
        #pragma unroll
        for (int r = 0; r < 8; r++){ acc0[r] = 0ULL; acc1[r] = 0ULL; }
        #pragma unroll 4
        for (int kq = 0; kq < 16; kq++){
            ulonglong2 w0 = *reinterpret_cast<const ulonglong2*>(&s_w4[kq*128 + cl]);
            ulonglong2 w1 = *reinterpret_cast<const ulonglong2*>(&s_w4[kq*128 + cl + 64]);
            #pragma unroll
            for (int r = 0; r < 8; r++){
                ulonglong2 c = *reinterpret_cast<const ulonglong2*>(&s_c[(rg*8 + r)*64 + 4*kq]);
                fma2(acc0[r], w0.x, c.x);
                fma2(acc0[r], w0.y, c.y);
                fma2(acc1[r], w1.x, c.x);
                fma2(acc1[r], w1.y, c.y);
            }
        }
        #pragma unroll
        for (int r = 0; r < 8; r++){
            size_t row = (size_t)(r0 + rg*8 + r);
            g_xg[row*G4 + j0] = hsum2(acc0[r]) + b0;
            g_xg[row*G4 + j1] = hsum2(acc1[r]) + b1;
        }
        __syncthreads();
    }
}

/* ============ kernel 3: recurrent LSTM scan + output GEMM ================
 * R13 shape; gate nonlinearities via HW tanh.approx (5 XU ops/cell vs 10):
 * sigmoid(x) = 0.5*tanh(x/2)+0.5.                                         */
__global__ void __launch_bounds__(512, 2) k_lstm(
    const float* __restrict__ Wout, const float* __restrict__ bout, float* __restrict__ outp)
{
    __shared__ __align__(16) float s_h[8*HIDD];    /* 4 KB  */
    __shared__ __align__(16) float s_g[64*HIDD];   /* 32 KB */
    const int tid = threadIdx.x;
    const int c   = tid & 255;                     /* owns cols c and c+256 */
    const int rh  = tid >> 8;                      /* rows 4rh..4rh+3 */
    const int b0  = blockIdx.x * 8;
    for (int i = tid; i < 8*HIDD; i += 512) s_h[i] = 0.f;
    float creg[2] = {0.f, 0.f};
    __syncthreads();

    const uint2* __restrict__ wp = g_whhh;

    for (int s = 0; s < SEQL; s++){
        const float* xgp = g_xg + ((size_t)s*BSZ + b0)*G4;
        float xv0[4], xv1[4];
        #pragma unroll
        for (int r = 0; r < 4; r++){
            int row = rh*4 + r;
            xv0[r] = __ldg(&xgp[(size_t)row*G4 + c]);
            xv1[r] = __ldg(&xgp[(size_t)row*G4 + c + 256]);
        }

        ull acc0[4], acc1[4];
        #pragma unroll
        for (int r = 0; r < 4; r++){ acc0[r] = 0ULL; acc1[r] = 0ULL; }

        #pragma unroll 4
        for (int kq = 0; kq < 32; kq++){
            uint2 u0 = __ldg(&wp[kq*G4 + c]);               /* LDG.64 coalesced */
            uint2 u1 = __ldg(&wp[kq*G4 + 256 + c]);
            ull w0a = h2f2(u0.x), w0b = h2f2(u0.y);
            ull w1a = h2f2(u1.x), w1b = h2f2(u1.y);
            ulonglong2 h[4];
            #pragma unroll
            for (int r = 0; r < 4; r++)
                h[r] = *reinterpret_cast<const ulonglong2*>(&s_h[(rh*4 + r)*HIDD + 4*kq]);
            #pragma unroll
            for (int r = 0; r < 4; r++){
                fma2(acc0[r], w0a, h[r].x);
                fma2(acc0[r], w0b, h[r].y);
                fma2(acc1[r], w1a, h[r].x);
                fma2(acc1[r], w1b, h[r].y);
            }
        }

        #pragma unroll
        for (int r = 0; r < 4; r++){
            int row = rh*4 + r;
            s_g[row*G4 + c]       = hsum2(acc0[r]) + xv0[r];
            s_g[row*G4 + c + 256] = hsum2(acc1[r]) + xv1[r];
        }
        __syncthreads();
        #pragma unroll
        for (int q = 0; q < 2; q++){                        /* 1024 cells / 512 thr */
            int cell = q*512 + tid;
            int r = cell >> 7, j = cell & 127;
            float ig = sigma(s_g[r*G4 + j]);
            float fg = sigma(s_g[r*G4 + 128 + j]);
            float gg = tanha(s_g[r*G4 + 256 + j]);
            float og = sigma(s_g[r*G4 + 384 + j]);
            float cc = fg*creg[q] + ig*gg;
            creg[q]  = cc;
            s_h[r*HIDD + j] = og * tanha(cc);
        }
        __syncthreads();
    }

    /* out = h_last @ W_out^T + b_out */
    float* s_wo = s_g;
    for (int i = tid; i < 64*HIDD; i += 512){
        int oo = i & 63, jj = i >> 6;
        s_wo[jj*64 + oo] = Wout[oo*HIDD + jj];
    }
    __syncthreads();
    {
        int r = tid >> 6, oo = tid & 63;
        float acc = __ldg(&bout[oo]);
        #pragma unroll 8
        for (int jj = 0; jj < HIDD; jj++) acc += s_wo[jj*64 + oo] * s_h[r*HIDD + jj];
        outp[(size_t)(b0 + r)*64 + oo] = acc;
    }
}

/* ======================================================================== */
extern "C" void kernel_launch(void* const* d_in, const int* in_sizes, int n_in,
                              void* d_out, int out_size)
{
    const float* seqs = (const float*)d_in[0];
    const float* ets  = (const float*)d_in[1];
    const int*   msk  = (const int*)  d_in[2];
    const float* Wfus = (const float*)d_in[3];
    const float* bfus = (const float*)d_in[4];
    const float* Wk   = (const float*)d_in[5];
    const float* bk   = (const float*)d_in[6];
    const float* Wq   = (const float*)d_in[7];
    const float* bq   = (const float*)d_in[8];
    const float* Wv   = (const float*)d_in[9];
    const float* bv   = (const float*)d_in[10];
    const float* Wih  = (const float*)d_in[11];
    const float* Whh  = (const float*)d_in[12];
    const float* bih  = (const float*)d_in[13];
    const float* bhh  = (const float*)d_in[14];
    const float* Wout = (const float*)d_in[15];
    const float* bout = (const float*)d_in[16];
    float* outp = (float*)d_out;

    k_prep<<<24, 128>>>(Wfus, bfus, Wk, bk, Wq, bq, Wv, bv);
    k_pack<<<32, 512>>>(Whh);
    k_ctx <<<592, 128>>>(seqs, ets, msk);
    k_xg  <<<888, 128>>>(Wih, bih, bhh);
    k_lstm<<<256, 512>>>(Wout, bout, outp);
}

// round 15
// speedup vs baseline: 1.8985x; 1.1704x over previous
#include <cuda_runtime.h>
#include <cuda_fp16.h>

#define BSZ  2048
#define SEQL 50
#define NP   (BSZ*SEQL)      /* 102400 pairs */
#define ATTD 64
#define HIDD 128
#define G4   512             /* 4*HID gates */

typedef unsigned long long ull;

/* ---------------- device scratch (no cudaMalloc allowed) ---------------- */
__device__ float  g_ctx[(size_t)NP * ATTD];        /* [s][b][64]  26 MB  */
__device__ float  g_xg [(size_t)NP * G4];          /* [s][b][512] 210 MB */
__device__ uint2  g_whhh[(HIDD/4) * G4];           /* [kq][col] fp16x4 W_hh^T */
__device__ float  g_M[4*7*20];                     /* bilinear att matrices */
__device__ float  g_G[20*64];                      /* folded Wv*Ffus (+bv)  */

/* ---------------- helpers ----------------------------------------------- */
__device__ __forceinline__ void fma2(ull& d, ull a, ull b){
    asm("fma.rn.f32x2 %0, %1, %2, %0;" : "+l"(d) : "l"(a), "l"(b));
}
__device__ __forceinline__ float2 unpk(ull v){
    float2 r; asm("mov.b64 {%0, %1}, %2;" : "=f"(r.x), "=f"(r.y) : "l"(v)); return r;
}
__device__ __forceinline__ float hsum2(ull v){ float2 f = unpk(v); return f.x + f.y; }
__device__ __forceinline__ ull h2f2(unsigned u){        /* half2 -> packed f32x2 */
    __half2 h = *reinterpret_cast<__half2*>(&u);
    float2 f = __half22float2(h);
    ull r; asm("mov.b64 %0, {%1, %2};" : "=l"(r) : "f"(f.x), "f"(f.y));
    return r;
}
__device__ __forceinline__ float tanha(float x){        /* HW tanh, 1 XU op */
    float r; asm("tanh.approx.f32 %0, %1;" : "=f"(r) : "f"(x)); return r;
}
__device__ __forceinline__ float sigma(float x){        /* sigmoid via tanh */
    return fmaf(0.5f, tanha(0.5f*x), 0.5f);
}

/* ============ kernel P: fold weights into M (4x7x20) and G (20x64) ====== */
__global__ void k_prep(
    const float* __restrict__ Wfus, const float* __restrict__ bfus,
    const float* __restrict__ Wk,   const float* __restrict__ bk,
    const float* __restrict__ Wq,   const float* __restrict__ bq,
    const float* __restrict__ Wv,   const float* __restrict__ bv)
{
    __shared__ float sQ[16*20];
    const int bid = blockIdx.x, tid = threadIdx.x;      /* <<<24,128>>> */
    if (bid < 4){
        int h = bid;
        for (int i = tid; i < 320; i += 128){
            int k = i % 20, d = i / 20, od = h*16 + d;
            float acc = (k == 19) ? bq[od] : 0.f;
            for (int c = 0; c < 64; c++){
                float f = (k < 19) ? Wfus[c*19 + k] : bfus[c];
                acc += Wq[od*64 + c] * f;
            }
            sQ[i] = acc;
        }
        __syncthreads();
        for (int i = tid; i < 140; i += 128){
            int k = i % 20, dp = i / 20;
            float acc = 0.f;
            for (int d = 0; d < 16; d++){
                int o = h*16 + d;
                float wk = (dp < 6) ? Wk[o*6 + dp] : bk[o];
                acc += wk * sQ[d*20 + k];
            }
            g_M[h*140 + dp*20 + k] = 0.25f * acc;
        }
    } else {
        int k = bid - 4;                                /* 0..19 */
        for (int o = tid; o < 64; o += 128){
            float acc = (k == 19) ? bv[o] : 0.f;
            for (int c = 0; c < 64; c++){
                float f = (k < 19) ? Wfus[c*19 + k] : bfus[c];
                acc += Wv[o*64 + c] * f;
            }
            g_G[k*64 + o] = acc;
        }
    }
}

/* ============ kernel 0: pack W_hh^T -> [kq][col] fp16x4 ================= */
__global__ void k_pack(const float* __restrict__ Whh){
    int t = threadIdx.x, kq = blockIdx.x;             /* <<<32,512>>> */
    __half2 a = __floats2half2_rn(Whh[t*HIDD + 4*kq],   Whh[t*HIDD + 4*kq+1]);
    __half2 b = __floats2half2_rn(Whh[t*HIDD + 4*kq+2], Whh[t*HIDD + 4*kq+3]);
    uint2 u;
    u.x = *reinterpret_cast<unsigned*>(&a);
    u.y = *reinterpret_cast<unsigned*>(&b);
    g_whhh[kq*G4 + t] = u;
}

/* ============ kernel 1: attention via precomputed bilinear form (R10) === */
__global__ void __launch_bounds__(128) k_ctx(
    const float* __restrict__ seqs, const float* __restrict__ ets,
    const int* __restrict__ masks)
{
    __shared__ __align__(16) float sM[560];
    __shared__ __align__(16) float sG[20*64];
    __shared__ __align__(16) float s_raw[2][96];
    __shared__ float s_t[2][4][20];
    __shared__ int s_msk[2][12];

    const int tid = threadIdx.x;
    for (int i = tid; i < 560;   i += 128) sM[i] = g_M[i];
    for (int i = tid; i < 20*64; i += 128) sG[i] = g_G[i];
    __syncthreads();

    const int g   = tid >> 6;
    const int o   = tid & 63;
    const int h   = o >> 4;
    const int cl  = o & 15;
    const int hb  = o & 16;                /* segment base within warp */
    const int bar = g + 1;
    const int ggid    = blockIdx.x*2 + g;
    const int ngroups = gridDim.x*2;
    const unsigned FULL = 0xffffffffu;
    const float* Mh = &sM[h*140];

    for (int pr = ggid; pr < NP; pr += ngroups){
        const float* sq = seqs + (size_t)pr*54;
        const float* se = ets  + (size_t)pr*36;
        for (int i = o; i < 90; i += 64) s_raw[g][i] = (i < 54) ? sq[i] : se[i-54];
        if (o < 9) s_msk[g][o] = masks[(size_t)pr*9 + o];
        asm volatile("bar.sync %0, 64;" :: "r"(bar) : "memory");
        const float* rg = s_raw[g];

        float xs[6];
        #pragma unroll
        for (int d = 0; d < 6; d++) xs[d] = rg[24 + d];

        /* t_h[k] = xs~^T M_h : lane cl covers k=cl (and k=16+cl for cl<4) */
        {
            float t1 = Mh[6*20 + cl];
            #pragma unroll
            for (int d = 0; d < 6; d++) t1 += xs[d] * Mh[d*20 + cl];
            s_t[g][h][cl] = t1;
            if (cl < 4){
                int k2 = 16 + cl;
                float t2 = Mh[6*20 + k2];
                #pragma unroll
                for (int d = 0; d < 6; d++) t2 += xs[d] * Mh[d*20 + k2];
                s_t[g][h][k2] = t2;
            }
        }
        __syncwarp();

        /* att for slot n=cl (<9): t.xn~ (one-hot -> direct t[10+n]) */
        float att;
        {
            int n = (cl < 9) ? cl : 8;
            const float* tp = s_t[g][h];
            float v = tp[19] + tp[10 + n];
            #pragma unroll
            for (int k = 0; k < 6; k++) v += tp[k] * rg[n*6 + k];
            #pragma unroll
            for (int j = 0; j < 4; j++) v += tp[6 + j] * rg[54 + n*4 + j];
            att = (cl < 9) ? ((s_msk[g][n] == 0) ? -1e10f : v) : -1e30f;
        }

        /* softmax over 9 inside 16-lane segment */
        float m = att;
        #pragma unroll
        for (int mm = 8; mm >= 1; mm >>= 1) m = fmaxf(m, __shfl_xor_sync(FULL, m, mm));
        float ex = __expf(att - m);
        float ssum = ex;
        #pragma unroll
        for (int mm = 8; mm >= 1; mm >>= 1) ssum += __shfl_xor_sync(FULL, ssum, mm);
        float inv = 1.f / ssum;
        float a[9];
        #pragma unroll
        for (int n = 0; n < 9; n++) a[n] = __shfl_sync(FULL, ex, hb | n) * inv;

        /* xbar[k<10] = sum_n a[n] xn[k]; lane kx=cl computes, then gather */
        float xb = 0.f;
        {
            int kx = (cl < 10) ? cl : 9;
            #pragma unroll
            for (int n = 0; n < 9; n++)
                xb += a[n] * ((kx < 6) ? rg[n*6 + kx] : rg[54 + n*4 + (kx - 6)]);
        }
        float xk[10];
        #pragma unroll
        for (int k = 0; k < 10; k++) xk[k] = __shfl_sync(FULL, xb, hb | k);

        /* ctx[o] = G[19][o] + sum_{k<10} xk G[k][o] + sum_n a_n G[10+n][o] */
        float c = sG[19*64 + o];
        #pragma unroll
        for (int k = 0; k < 10; k++) c += xk[k] * sG[k*64 + o];
        #pragma unroll
        for (int n = 0; n < 9; n++) c += a[n] * sG[(10+n)*64 + o];

        int b = pr / SEQL, s = pr - b*SEQL;            /* time-major for LSTM */
        g_ctx[((size_t)s*BSZ + b)*ATTD + o] = c;
        asm volatile("bar.sync %0, 64;" :: "r"(bar) : "memory");
    }
}

/* ============ kernel 2: xg = ctx @ W_ih^T + b via tensor cores ==========
 * mma.sync.m16n8k16 f16 inputs / f32 accum. Block = 256 thr (8 warps),
 * tile = 64 rows x 256 cols (one col-half of the 512 gates). Fragments
 * loaded by explicit LDS.32 half2 (stride-72 padding -> conflict-free).
 * Bias preloaded into accumulators.                                       */
__global__ void __launch_bounds__(256) k_xg(
    const float* __restrict__ Wih, const float* __restrict__ bih, const float* __restrict__ bhh)
{
    __shared__ __half sB[256*72];                  /* W_ih col-half, fp16, 36KB */
    __shared__ __half sA[64*72];                   /* ctx tile, fp16, 9KB */
    __shared__ float  s_b[256];
    const int tid  = threadIdx.x;
    const int cg   = blockIdx.x & 1;               /* col half 0/1 */
    const int rb   = blockIdx.x >> 1;              /* 0..591 */
    const int lane = tid & 31;
    const int w    = tid >> 5;
    const int g    = lane >> 2;
    const int t    = lane & 3;
    const int rowoff = (w & 3) * 16;               /* warp row tile */
    const int coff   = (w >> 2) * 128;             /* warp col range in half */

    for (int i = tid; i < 256*64; i += 256){
        int j = i >> 6, k = i & 63;
        sB[j*72 + k] = __float2half(Wih[(cg*256 + j)*64 + k]);
    }
    s_b[tid] = bih[cg*256 + tid] + bhh[cg*256 + tid];
    __syncthreads();

    for (int rt = rb; rt < 1600; rt += 592){
        const float* cs = g_ctx + (size_t)rt*64*64;
        for (int i = tid; i < 64*64; i += 256){
            sA[(i >> 6)*72 + (i & 63)] = __float2half(cs[i]);
        }
        __syncthreads();

        float acc[16][4];
        #pragma unroll
        for (int nt = 0; nt < 16; nt++){
            int cl2 = coff + nt*8 + 2*t;
            float bb0 = s_b[cl2], bb1 = s_b[cl2 + 1];
            acc[nt][0] = bb0; acc[nt][1] = bb1;
            acc[nt][2] = bb0; acc[nt][3] = bb1;
        }

        #pragma unroll
        for (int ks = 0; ks < 4; ks++){
            unsigned a0 = *reinterpret_cast<const unsigned*>(&sA[(rowoff + g    )*72 + ks*16 + 2*t    ]);
            unsigned a1 = *reinterpret_cast<const unsigned*>(&sA[(rowoff + g + 8)*72 + ks*16 + 2*t    ]);
            unsigned a2 = *reinterpret_cast<const unsigned*>(&sA[(rowoff + g    )*72 + ks*16 + 2*t + 8]);
            unsigned a3 = *reinterpret_cast<const unsigned*>(&sA[(rowoff + g + 8)*72 + ks*16 + 2*t + 8]);
            #pragma unroll
            for (int nt = 0; nt < 16; nt++){
                int nl = coff + nt*8 + g;
                unsigned b0 = *reinterpret_cast<const unsigned*>(&sB[nl*72 + ks*16 + 2*t    ]);
                unsigned b1 = *reinterpret_cast<const unsigned*>(&sB[nl*72 + ks*16 + 2*t + 8]);
                asm volatile(
                    "mma.sync.aligned.m16n8k16.row.col.f32.f16.f16.f32 "
                    "{%0,%1,%2,%3}, {%4,%5,%6,%7}, {%8,%9}, {%0,%1,%2,%3};"
                    : "+f"(acc[nt][0]), "+f"(acc[nt][1]), "+f"(acc[nt][2]), "+f"(acc[nt][3])
                    : "r"(a0), "r"(a1), "r"(a2), "r"(a3), "r"(b0), "r"(b1));
            }
        }

        int rowa = rt*64 + rowoff + g;
        #pragma unroll
        for (int nt = 0; nt < 16; nt++){
            int col = cg*256 + coff + nt*8 + 2*t;
            *reinterpret_cast<float2*>(&g_xg[(size_t)rowa*G4 + col]) =
                make_float2(acc[nt][0], acc[nt][1]);
            *reinterpret_cast<float2*>(&g_xg[(size_t)(rowa + 8)*G4 + col]) =
                make_float2(acc[nt][2], acc[nt][3]);
        }
        __syncthreads();
    }
}

/* ============ kernel 3: recurrent LSTM scan + output GEMM (R14) ========= */
__global__ void __launch_bounds__(512, 2) k_lstm(
    const float* __restrict__ Wout, const float* __restrict__ bout, float* __restrict__ outp)
{
    __shared__ __align__(16) float s_h[8*HIDD];    /* 4 KB  */
    __shared__ __align__(16) float s_g[64*HIDD];   /* 32 KB */
    const int tid = threadIdx.x;
    const int c   = tid & 255;                     /* owns cols c and c+256 */
    const int rh  = tid >> 8;                      /* rows 4rh..4rh+3 */
    const int b0  = blockIdx.x * 8;
    for (int i = tid; i < 8*HIDD; i += 512) s_h[i] = 0.f;
    float creg[2] = {0.f, 0.f};
    __syncthreads();

    const uint2* __restrict__ wp = g_whhh;

    for (int s = 0; s < SEQL; s++){
        const float* xgp = g_xg + ((size_t)s*BSZ + b0)*G4;
        float xv0[4], xv1[4];
        #pragma unroll
        for (int r = 0; r < 4; r++){
            int row = rh*4 + r;
            xv0[r] = __ldg(&xgp[(size_t)row*G4 + c]);
            xv1[r] = __ldg(&xgp[(size_t)row*G4 + c + 256]);
        }

        ull acc0[4], acc1[4];
        #pragma unroll
        for (int r = 0; r < 4; r++){ acc0[r] = 0ULL; acc1[r] = 0ULL; }

        #pragma unroll 4
        for (int kq = 0; kq < 32; kq++){
            uint2 u0 = __ldg(&wp[kq*G4 + c]);               /* LDG.64 coalesced */
            uint2 u1 = __ldg(&wp[kq*G4 + 256 + c]);
            ull w0a = h2f2(u0.x), w0b = h2f2(u0.y);
            ull w1a = h2f2(u1.x), w1b = h2f2(u1.y);
            ulonglong2 h[4];
            #pragma unroll
            for (int r = 0; r < 4; r++)
                h[r] = *reinterpret_cast<const ulonglong2*>(&s_h[(rh*4 + r)*HIDD + 4*kq]);
            #pragma unroll
            for (int r = 0; r < 4; r++){
                fma2(acc0[r], w0a, h[r].x);
                fma2(acc0[r], w0b, h[r].y);
                fma2(acc1[r], w1a, h[r].x);
                fma2(acc1[r], w1b, h[r].y);
            }
        }

        #pragma unroll
        for (int r = 0; r < 4; r++){
            int row = rh*4 + r;
            s_g[row*G4 + c]       = hsum2(acc0[r]) + xv0[r];
            s_g[row*G4 + c + 256] = hsum2(acc1[r]) + xv1[r];
        }
        __syncthreads();
        #pragma unroll
        for (int q = 0; q < 2; q++){                        /* 1024 cells / 512 thr */
            int cell = q*512 + tid;
            int r = cell >> 7, j = cell & 127;
            float ig = sigma(s_g[r*G4 + j]);
            float fg = sigma(s_g[r*G4 + 128 + j]);
            float gg = tanha(s_g[r*G4 + 256 + j]);
            float og = sigma(s_g[r*G4 + 384 + j]);
            float cc = fg*creg[q] + ig*gg;
            creg[q]  = cc;
            s_h[r*HIDD + j] = og * tanha(cc);
        }
        __syncthreads();
    }

    /* out = h_last @ W_out^T + b_out */
    float* s_wo = s_g;
    for (int i = tid; i < 64*HIDD; i += 512){
        int oo = i & 63, jj = i >> 6;
        s_wo[jj*64 + oo] = Wout[oo*HIDD + jj];
    }
    __syncthreads();
    {
        int r = tid >> 6, oo = tid & 63;
        float acc = __ldg(&bout[oo]);
        #pragma unroll 8
        for (int jj = 0; jj < HIDD; jj++) acc += s_wo[jj*64 + oo] * s_h[r*HIDD + jj];
        outp[(size_t)(b0 + r)*64 + oo] = acc;
    }
}

/* ======================================================================== */
extern "C" void kernel_launch(void* const* d_in, const int* in_sizes, int n_in,
                              void* d_out, int out_size)
{
    const float* seqs = (const float*)d_in[0];
    const float* ets  = (const float*)d_in[1];
    const int*   msk  = (const int*)  d_in[2];
    const float* Wfus = (const float*)d_in[3];
    const float* bfus = (const float*)d_in[4];
    const float* Wk   = (const float*)d_in[5];
    const float* bk   = (const float*)d_in[6];
    const float* Wq   = (const float*)d_in[7];
    const float* bq   = (const float*)d_in[8];
    const float* Wv   = (const float*)d_in[9];
    const float* bv   = (const float*)d_in[10];
    const float* Wih  = (const float*)d_in[11];
    const float* Whh  = (const float*)d_in[12];
    const float* bih  = (const float*)d_in[13];
    const float* bhh  = (const float*)d_in[14];
    const float* Wout = (const float*)d_in[15];
    const float* bout = (const float*)d_in[16];
    float* outp = (float*)d_out;

    k_prep<<<24, 128>>>(Wfus, bfus, Wk, bk, Wq, bq, Wv, bv);
    k_pack<<<32, 512>>>(Whh);
    k_ctx <<<592, 128>>>(seqs, ets, msk);
    k_xg  <<<1184, 256>>>(Wih, bih, bhh);
    k_lstm<<<256, 512>>>(Wout, bout, outp);
}

// round 16
// speedup vs baseline: 3.1483x; 1.6583x over previous
#include <cuda_runtime.h>
#include <cuda_fp16.h>

#define BSZ  2048
#define SEQL 50
#define NP   (BSZ*SEQL)      /* 102400 pairs */
#define ATTD 64
#define HIDD 128
#define G4   512             /* 4*HID gates */

typedef unsigned long long ull;

/* ---------------- device scratch (no cudaMalloc allowed) ---------------- */
__device__ float  g_ctx[(size_t)NP * ATTD];        /* [s][b][64]  26 MB  */
__device__ float  g_xg [(size_t)NP * G4];          /* [s][b][512] 210 MB */
__device__ float  g_M[4*7*20];                     /* bilinear att matrices */
__device__ float  g_G[20*64];                      /* folded Wv*Ffus (+bv)  */

/* ---------------- helpers ----------------------------------------------- */
__device__ __forceinline__ float tanha(float x){        /* HW tanh, 1 XU op */
    float r; asm("tanh.approx.f32 %0, %1;" : "=f"(r) : "f"(x)); return r;
}
__device__ __forceinline__ float sigma(float x){        /* sigmoid via tanh */
    return fmaf(0.5f, tanha(0.5f*x), 0.5f);
}

/* ============ kernel P: fold weights into M (4x7x20) and G (20x64) ====== */
__global__ void k_prep(
    const float* __restrict__ Wfus, const float* __restrict__ bfus,
    const float* __restrict__ Wk,   const float* __restrict__ bk,
    const float* __restrict__ Wq,   const float* __restrict__ bq,
    const float* __restrict__ Wv,   const float* __restrict__ bv)
{
    __shared__ float sQ[16*20];
    const int bid = blockIdx.x, tid = threadIdx.x;      /* <<<24,128>>> */
    if (bid < 4){
        int h = bid;
        for (int i = tid; i < 320; i += 128){
            int k = i % 20, d = i / 20, od = h*16 + d;
            float acc = (k == 19) ? bq[od] : 0.f;
            for (int c = 0; c < 64; c++){
                float f = (k < 19) ? Wfus[c*19 + k] : bfus[c];
                acc += Wq[od*64 + c] * f;
            }
            sQ[i] = acc;
        }
        __syncthreads();
        for (int i = tid; i < 140; i += 128){
            int k = i % 20, dp = i / 20;
            float acc = 0.f;
            for (int d = 0; d < 16; d++){
                int o = h*16 + d;
                float wk = (dp < 6) ? Wk[o*6 + dp] : bk[o];
                acc += wk * sQ[d*20 + k];
            }
            g_M[h*140 + dp*20 + k] = 0.25f * acc;
        }
    } else {
        int k = bid - 4;                                /* 0..19 */
        for (int o = tid; o < 64; o += 128){
            float acc = (k == 19) ? bv[o] : 0.f;
            for (int c = 0; c < 64; c++){
                float f = (k < 19) ? Wfus[c*19 + k] : bfus[c];
                acc += Wv[o*64 + c] * f;
            }
            g_G[k*64 + o] = acc;
        }
    }
}

/* ============ kernel 1: attention via precomputed bilinear form (R10) === */
__global__ void __launch_bounds__(128) k_ctx(
    const float* __restrict__ seqs, const float* __restrict__ ets,
    const int* __restrict__ masks)
{
    __shared__ __align__(16) float sM[560];
    __shared__ __align__(16) float sG[20*64];
    __shared__ __align__(16) float s_raw[2][96];
    __shared__ float s_t[2][4][20];
    __shared__ int s_msk[2][12];

    const int tid = threadIdx.x;
    for (int i = tid; i < 560;   i += 128) sM[i] = g_M[i];
    for (int i = tid; i < 20*64; i += 128) sG[i] = g_G[i];
    __syncthreads();

    const int g   = tid >> 6;
    const int o   = tid & 63;
    const int h   = o >> 4;
    const int cl  = o & 15;
    const int hb  = o & 16;                /* segment base within warp */
    const int bar = g + 1;
    const int ggid    = blockIdx.x*2 + g;
    const int ngroups = gridDim.x*2;
    const unsigned FULL = 0xffffffffu;
    const float* Mh = &sM[h*140];

    for (int pr = ggid; pr < NP; pr += ngroups){
        const float* sq = seqs + (size_t)pr*54;
        const float* se = ets  + (size_t)pr*36;
        for (int i = o; i < 90; i += 64) s_raw[g][i] = (i < 54) ? sq[i] : se[i-54];
        if (o < 9) s_msk[g][o] = masks[(size_t)pr*9 + o];
        asm volatile("bar.sync %0, 64;" :: "r"(bar) : "memory");
        const float* rg = s_raw[g];

        float xs[6];
        #pragma unroll
        for (int d = 0; d < 6; d++) xs[d] = rg[24 + d];

        {
            float t1 = Mh[6*20 + cl];
            #pragma unroll
            for (int d = 0; d < 6; d++) t1 += xs[d] * Mh[d*20 + cl];
            s_t[g][h][cl] = t1;
            if (cl < 4){
                int k2 = 16 + cl;
                float t2 = Mh[6*20 + k2];
                #pragma unroll
                for (int d = 0; d < 6; d++) t2 += xs[d] * Mh[d*20 + k2];
                s_t[g][h][k2] = t2;
            }
        }
        __syncwarp();

        float att;
        {
            int n = (cl < 9) ? cl : 8;
            const float* tp = s_t[g][h];
            float v = tp[19] + tp[10 + n];
            #pragma unroll
            for (int k = 0; k < 6; k++) v += tp[k] * rg[n*6 + k];
            #pragma unroll
            for (int j = 0; j < 4; j++) v += tp[6 + j] * rg[54 + n*4 + j];
            att = (cl < 9) ? ((s_msk[g][n] == 0) ? -1e10f : v) : -1e30f;
        }

        float m = att;
        #pragma unroll
        for (int mm = 8; mm >= 1; mm >>= 1) m = fmaxf(m, __shfl_xor_sync(FULL, m, mm));
        float ex = __expf(att - m);
        float ssum = ex;
        #pragma unroll
        for (int mm = 8; mm >= 1; mm >>= 1) ssum += __shfl_xor_sync(FULL, ssum, mm);
        float inv = 1.f / ssum;
        float a[9];
        #pragma unroll
        for (int n = 0; n < 9; n++) a[n] = __shfl_sync(FULL, ex, hb | n) * inv;

        float xb = 0.f;
        {
            int kx = (cl < 10) ? cl : 9;
            #pragma unroll
            for (int n = 0; n < 9; n++)
                xb += a[n] * ((kx < 6) ? rg[n*6 + kx] : rg[54 + n*4 + (kx - 6)]);
        }
        float xk[10];
        #pragma unroll
        for (int k = 0; k < 10; k++) xk[k] = __shfl_sync(FULL, xb, hb | k);

        float c = sG[19*64 + o];
        #pragma unroll
        for (int k = 0; k < 10; k++) c += xk[k] * sG[k*64 + o];
        #pragma unroll
        for (int n = 0; n < 9; n++) c += a[n] * sG[(10+n)*64 + o];

        int b = pr / SEQL, s = pr - b*SEQL;            /* time-major for LSTM */
        g_ctx[((size_t)s*BSZ + b)*ATTD + o] = c;
        asm volatile("bar.sync %0, 64;" :: "r"(bar) : "memory");
    }
}

/* ============ kernel 2: xg = ctx @ W_ih^T + b via tensor cores (R15) ==== */
__global__ void __launch_bounds__(256) k_xg(
    const float* __restrict__ Wih, const float* __restrict__ bih, const float* __restrict__ bhh)
{
    __shared__ __half sB[256*72];                  /* W_ih col-half, fp16, 36KB */
    __shared__ __half sA[64*72];                   /* ctx tile, fp16, 9KB */
    __shared__ float  s_b[256];
    const int tid  = threadIdx.x;
    const int cg   = blockIdx.x & 1;
    const int rb   = blockIdx.x >> 1;              /* 0..591 */
    const int lane = tid & 31;
    const int w    = tid >> 5;
    const int g    = lane >> 2;
    const int t    = lane & 3;
    const int rowoff = (w & 3) * 16;
    const int coff   = (w >> 2) * 128;

    for (int i = tid; i < 256*64; i += 256){
        int j = i >> 6, k = i & 63;
        sB[j*72 + k] = __float2half(Wih[(cg*256 + j)*64 + k]);
    }
    s_b[tid] = bih[cg*256 + tid] + bhh[cg*256 + tid];
    __syncthreads();

    for (int rt = rb; rt < 1600; rt += 592){
        const float* cs = g_ctx + (size_t)rt*64*64;
        for (int i = tid; i < 64*64; i += 256){
            sA[(i >> 6)*72 + (i & 63)] = __float2half(cs[i]);
        }
        __syncthreads();

        float acc[16][4];
        #pragma unroll
        for (int nt = 0; nt < 16; nt++){
            int cl2 = coff + nt*8 + 2*t;
            float bb0 = s_b[cl2], bb1 = s_b[cl2 + 1];
            acc[nt][0] = bb0; acc[nt][1] = bb1;
            acc[nt][2] = bb0; acc[nt][3] = bb1;
        }

        #pragma unroll
        for (int ks = 0; ks < 4; ks++){
            unsigned a0 = *reinterpret_cast<const unsigned*>(&sA[(rowoff + g    )*72 + ks*16 + 2*t    ]);
            unsigned a1 = *reinterpret_cast<const unsigned*>(&sA[(rowoff + g + 8)*72 + ks*16 + 2*t    ]);
            unsigned a2 = *reinterpret_cast<const unsigned*>(&sA[(rowoff + g    )*72 + ks*16 + 2*t + 8]);
            unsigned a3 = *reinterpret_cast<const unsigned*>(&sA[(rowoff + g + 8)*72 + ks*16 + 2*t + 8]);
            #pragma unroll
            for (int nt = 0; nt < 16; nt++){
                int nl = coff + nt*8 + g;
                unsigned b0 = *reinterpret_cast<const unsigned*>(&sB[nl*72 + ks*16 + 2*t    ]);
                unsigned b1 = *reinterpret_cast<const unsigned*>(&sB[nl*72 + ks*16 + 2*t + 8]);
                asm volatile(
                    "mma.sync.aligned.m16n8k16.row.col.f32.f16.f16.f32 "
                    "{%0,%1,%2,%3}, {%4,%5,%6,%7}, {%8,%9}, {%0,%1,%2,%3};"
                    : "+f"(acc[nt][0]), "+f"(acc[nt][1]), "+f"(acc[nt][2]), "+f"(acc[nt][3])
                    : "r"(a0), "r"(a1), "r"(a2), "r"(a3), "r"(b0), "r"(b1));
            }
        }

        int rowa = rt*64 + rowoff + g;
        #pragma unroll
        for (int nt = 0; nt < 16; nt++){
            int col = cg*256 + coff + nt*8 + 2*t;
            *reinterpret_cast<float2*>(&g_xg[(size_t)rowa*G4 + col]) =
                make_float2(acc[nt][0], acc[nt][1]);
            *reinterpret_cast<float2*>(&g_xg[(size_t)(rowa + 8)*G4 + col]) =
                make_float2(acc[nt][2], acc[nt][3]);
        }
        __syncthreads();
    }
}

/* ============ kernel 3: LSTM scan, tensor-core GEMM, smem weights =======
 * 128 blocks x 256 thr, 1 block/SM. W_hh fp16 resident in smem (139KB,
 * loaded once); h fp16 in smem; per step one m16 x n512 x k128 mma chain
 * (8 warps x 8 n-tiles x 8 k-steps). Zero per-step weight traffic.        */
__global__ void __launch_bounds__(256) k_lstm(
    const float* __restrict__ Whh, const float* __restrict__ Wout,
    const float* __restrict__ bout, float* __restrict__ outp)
{
    extern __shared__ char dyn[];
    __half* sW  = reinterpret_cast<__half*>(dyn);            /* [512][136] 139264B */
    __half* sA  = reinterpret_cast<__half*>(dyn + 139264);   /* [16][136]   4352B  */
    float*  s_g = reinterpret_cast<float*>(dyn + 143616);    /* [16][512]  32768B  */

    const int tid  = threadIdx.x;
    const int lane = tid & 31;
    const int w    = tid >> 5;
    const int g    = lane >> 2;
    const int t    = lane & 3;
    const int coff = w * 64;                 /* warp's 64 gate cols */
    const int hi   = tid >> 7;               /* 0/1 row-parity for gates */
    const int j    = tid & 127;              /* gate cell column */
    const int b0   = blockIdx.x * 16;

    /* load W_hh fp16 into smem once: sW[n][k], n=gate row, k=hidden */
    for (int i = tid; i < 512*128; i += 256){
        int n = i >> 7, k = i & 127;
        sW[n*136 + k] = __float2half(Whh[n*HIDD + k]);
    }
    for (int i = tid; i < 16*136; i += 256) sA[i] = __float2half(0.f);
    float creg[8];
    #pragma unroll
    for (int q = 0; q < 8; q++) creg[q] = 0.f;
    __syncthreads();

    for (int s = 0; s < SEQL; s++){
        /* prefetch xg for own 8 cells (row = q*2+hi, col j), coalesced */
        const float* xgp = g_xg + ((size_t)s*BSZ + b0)*G4;
        float xi[8], xf[8], xgv[8], xo[8];
        #pragma unroll
        for (int q = 0; q < 8; q++){
            const float* xr = xgp + (size_t)(q*2 + hi)*G4;
            xi[q]  = __ldg(&xr[j]);
            xf[q]  = __ldg(&xr[128 + j]);
            xgv[q] = __ldg(&xr[256 + j]);
            xo[q]  = __ldg(&xr[384 + j]);
        }

        /* h @ W_hh^T via mma: A = sA [16][128], B = sW [512][128] col-maj */
        float acc[8][4];
        #pragma unroll
        for (int nt = 0; nt < 8; nt++){
            acc[nt][0] = 0.f; acc[nt][1] = 0.f; acc[nt][2] = 0.f; acc[nt][3] = 0.f;
        }
        #pragma unroll
        for (int ks = 0; ks < 8; ks++){
            unsigned a0 = *reinterpret_cast<const unsigned*>(&sA[(g    )*136 + ks*16 + 2*t    ]);
            unsigned a1 = *reinterpret_cast<const unsigned*>(&sA[(g + 8)*136 + ks*16 + 2*t    ]);
            unsigned a2 = *reinterpret_cast<const unsigned*>(&sA[(g    )*136 + ks*16 + 2*t + 8]);
            unsigned a3 = *reinterpret_cast<const unsigned*>(&sA[(g + 8)*136 + ks*16 + 2*t + 8]);
            #pragma unroll
            for (int nt = 0; nt < 8; nt++){
                int nl = coff + nt*8 + g;
                unsigned b0f = *reinterpret_cast<const unsigned*>(&sW[nl*136 + ks*16 + 2*t    ]);
                unsigned b1f = *reinterpret_cast<const unsigned*>(&sW[nl*136 + ks*16 + 2*t + 8]);
                asm volatile(
                    "mma.sync.aligned.m16n8k16.row.col.f32.f16.f16.f32 "
                    "{%0,%1,%2,%3}, {%4,%5,%6,%7}, {%8,%9}, {%0,%1,%2,%3};"
                    : "+f"(acc[nt][0]), "+f"(acc[nt][1]), "+f"(acc[nt][2]), "+f"(acc[nt][3])
                    : "r"(a0), "r"(a1), "r"(a2), "r"(a3), "r"(b0f), "r"(b1f));
            }
        }
        /* stage gates to s_g */
        #pragma unroll
        for (int nt = 0; nt < 8; nt++){
            int col = coff + nt*8 + 2*t;
            *reinterpret_cast<float2*>(&s_g[(g    )*G4 + col]) = make_float2(acc[nt][0], acc[nt][1]);
            *reinterpret_cast<float2*>(&s_g[(g + 8)*G4 + col]) = make_float2(acc[nt][2], acc[nt][3]);
        }
        __syncthreads();

        /* gate phase: 8 cells/thread (rows q*2+hi, col j) */
        #pragma unroll
        for (int q = 0; q < 8; q++){
            int r = q*2 + hi;
            float ig = sigma(s_g[r*G4 + j]       + xi[q]);
            float fg = sigma(s_g[r*G4 + 128 + j] + xf[q]);
            float gg = tanha(s_g[r*G4 + 256 + j] + xgv[q]);
            float og = sigma(s_g[r*G4 + 384 + j] + xo[q]);
            float cc = fg*creg[q] + ig*gg;
            creg[q]  = cc;
            sA[r*136 + j] = __float2half(og * tanha(cc));
        }
        __syncthreads();
    }

    /* out = h_last @ W_out^T + b_out ; stage W_out^T [jj][oo] in s_g */
    float* s_wo = s_g;
    for (int i = tid; i < 64*HIDD; i += 256){
        int oo = i & 63, jj = i >> 6;
        s_wo[jj*64 + oo] = Wout[oo*HIDD + jj];
    }
    __syncthreads();
    #pragma unroll
    for (int q = 0; q < 4; q++){             /* 1024 outputs / 256 thr */
        int idx = q*256 + tid;
        int r = idx >> 6, oo = idx & 63;
        float acc = __ldg(&bout[oo]);
        #pragma unroll 8
        for (int jj = 0; jj < HIDD; jj++)
            acc += s_wo[jj*64 + oo] * __half2float(sA[r*136 + jj]);
        outp[(size_t)(b0 + r)*64 + oo] = acc;
    }
}

/* ======================================================================== */
extern "C" void kernel_launch(void* const* d_in, const int* in_sizes, int n_in,
                              void* d_out, int out_size)
{
    const float* seqs = (const float*)d_in[0];
    const float* ets  = (const float*)d_in[1];
    const int*   msk  = (const int*)  d_in[2];
    const float* Wfus = (const float*)d_in[3];
    const float* bfus = (const float*)d_in[4];
    const float* Wk   = (const float*)d_in[5];
    const float* bk   = (const float*)d_in[6];
    const float* Wq   = (const float*)d_in[7];
    const float* bq   = (const float*)d_in[8];
    const float* Wv   = (const float*)d_in[9];
    const float* bv   = (const float*)d_in[10];
    const float* Wih  = (const float*)d_in[11];
    const float* Whh  = (const float*)d_in[12];
    const float* bih  = (const float*)d_in[13];
    const float* bhh  = (const float*)d_in[14];
    const float* Wout = (const float*)d_in[15];
    const float* bout = (const float*)d_in[16];
    float* outp = (float*)d_out;

    const int lstm_smem = 139264 + 4352 + 32768;   /* 176384 B */
    cudaFuncSetAttribute(k_lstm, cudaFuncAttributeMaxDynamicSharedMemorySize, lstm_smem);

    k_prep<<<24, 128>>>(Wfus, bfus, Wk, bk, Wq, bq, Wv, bv);
    k_ctx <<<592, 128>>>(seqs, ets, msk);
    k_xg  <<<1184, 256>>>(Wih, bih, bhh);
    k_lstm<<<128, 256, lstm_smem>>>(Whh, Wout, bout, outp);
}